// round 10
// baseline (speedup 1.0000x reference)
#include <cuda_runtime.h>
#include <cuda_bf16.h>
#include <math.h>
#include <stdint.h>

#define B 2048
#define C1 15
#define C2 30
#define P1 29
#define P2 11
#define IN2P 32
#define FC1_IN (30*11*11)
#define FC1_OUT 200
#define KSPLIT 8
#define NKS1 227              // ceil(3630/16)

typedef unsigned long long ull;
typedef __nv_bfloat16 bf16;
typedef uint16_t u16;
typedef uint32_t u32;

// ---------------- warp mma m16n8k16 bf16 ----------------
__device__ __forceinline__ void mma_bf16(float* d, u32 a0, u32 a1, u32 a2, u32 a3,
                                         u32 b0, u32 b1) {
    asm volatile(
        "mma.sync.aligned.m16n8k16.row.col.f32.bf16.bf16.f32 "
        "{%0,%1,%2,%3}, {%4,%5,%6,%7}, {%8,%9}, {%0,%1,%2,%3};"
        : "+f"(d[0]), "+f"(d[1]), "+f"(d[2]), "+f"(d[3])
        : "r"(a0), "r"(a1), "r"(a2), "r"(a3), "r"(b0), "r"(b1));
}

__device__ __forceinline__ u16 bf16_bits(float v) {
    return __bfloat16_as_ushort(__float2bfloat16(v));
}

// ---------------- scratch ----------------
__device__ float g_p1[B * C1 * P1 * IN2P];
__device__ float g_fc1p[KSPLIT * B * FC1_OUT];
__device__ __align__(16) u32 g_Bfrag2[60 * 4 * 32 * 4];      // conv2 B frags
__device__ __align__(16) uint4 g_B1frag[2 * 4 * 32];          // conv1 B frags
__device__ __align__(16) uint4 g_W1frag[NKS1 * 25 * 32];      // fc1 W frags
__device__ __align__(4) u16 g_p2h[B * FC1_IN + 64];
__device__ __align__(4) u16 g_p2l[B * FC1_IN + 64];

// ---------------- kernel 0a: prep conv2 B fragments ----------------
__global__ void prep_b_frag(const float* __restrict__ w2)
{
    int idx = blockIdx.x * 256 + threadIdx.x;
    if (idx >= 7680) return;
    int lane = idx & 31, nt = (idx >> 5) & 3, ks = idx >> 7;
    int ic = ks >> 2, dyp = ks & 3;
    int oc = nt * 8 + (lane >> 2), k0 = (lane & 3) * 2;
    int dy0 = dyp * 2, dy1 = dy0 + 1;

    float v[4] = {0.f, 0.f, 0.f, 0.f};
    if (oc < C2) {
        const float* wb = w2 + (oc * C1 + ic) * 49;
        v[0] = wb[dy0 * 7 + k0];
        if (k0 + 1 < 7) v[1] = wb[dy0 * 7 + k0 + 1];
        if (dy1 < 7) {
            v[2] = wb[dy1 * 7 + k0];
            if (k0 + 1 < 7) v[3] = wb[dy1 * 7 + k0 + 1];
        }
    }
    u16 h[4], l[4];
    #pragma unroll
    for (int i = 0; i < 4; i++) {
        h[i] = bf16_bits(v[i]);
        l[i] = bf16_bits(v[i] - __uint_as_float((u32)h[i] << 16));
    }
    uint4 q;
    q.x = (u32)h[0] | ((u32)h[1] << 16);
    q.y = (u32)h[2] | ((u32)h[3] << 16);
    q.z = (u32)l[0] | ((u32)l[1] << 16);
    q.w = (u32)l[2] | ((u32)l[3] << 16);
    ((uint4*)g_Bfrag2)[idx] = q;
}

// ---------------- kernel 0b: prep conv1 B fragments (2 nt x 4 ks x 32) ----------------
__global__ void prep_b1_frag(const float* __restrict__ w1)
{
    int idx = threadIdx.x;               // 256 threads
    int lane = idx & 31, ks = (idx >> 5) & 3, nt = idx >> 7;
    int oc = nt * 8 + (lane >> 2), k0 = (lane & 3) * 2;
    int dy0 = ks * 2, dy1 = dy0 + 1;

    float v[4] = {0.f, 0.f, 0.f, 0.f};
    if (oc < C1) {
        const float* wb = w1 + oc * 49;
        if (dy0 < 7) {
            v[0] = wb[dy0 * 7 + k0];
            if (k0 + 1 < 7) v[1] = wb[dy0 * 7 + k0 + 1];
        }
        if (dy1 < 7) {
            v[2] = wb[dy1 * 7 + k0];
            if (k0 + 1 < 7) v[3] = wb[dy1 * 7 + k0 + 1];
        }
    }
    u16 h[4], l[4];
    #pragma unroll
    for (int i = 0; i < 4; i++) {
        h[i] = bf16_bits(v[i]);
        l[i] = bf16_bits(v[i] - __uint_as_float((u32)h[i] << 16));
    }
    uint4 q;
    q.x = (u32)h[0] | ((u32)h[1] << 16);
    q.y = (u32)h[2] | ((u32)h[3] << 16);
    q.z = (u32)l[0] | ((u32)l[1] << 16);
    q.w = (u32)l[2] | ((u32)l[3] << 16);
    g_B1frag[(nt * 4 + ks) * 32 + lane] = q;
}

// ---------------- kernel 0c: prep fc1 W fragments ----------------
__global__ void prep_w1_frag(const float* __restrict__ w)
{
    int idx = blockIdx.x * 256 + threadIdx.x;
    if (idx >= NKS1 * 25 * 32) return;
    int lane = idx & 31;
    int nt = (idx >> 5) % 25;
    int ks = idx / (25 * 32);
    int o = nt * 8 + (lane >> 2);
    int k0 = ks * 16 + (lane & 3) * 2;
    const float* wr = w + (size_t)o * FC1_IN;

    float v[4];
    v[0] = (k0     < FC1_IN) ? wr[k0]     : 0.f;
    v[1] = (k0 + 1 < FC1_IN) ? wr[k0 + 1] : 0.f;
    v[2] = (k0 + 8 < FC1_IN) ? wr[k0 + 8] : 0.f;
    v[3] = (k0 + 9 < FC1_IN) ? wr[k0 + 9] : 0.f;
    u16 h[4], l[4];
    #pragma unroll
    for (int i = 0; i < 4; i++) {
        h[i] = bf16_bits(v[i]);
        l[i] = bf16_bits(v[i] - __uint_as_float((u32)h[i] << 16));
    }
    uint4 q;
    q.x = (u32)h[0] | ((u32)h[1] << 16);
    q.y = (u32)h[2] | ((u32)h[3] << 16);
    q.z = (u32)l[0] | ((u32)l[1] << 16);
    q.w = (u32)l[2] | ((u32)l[3] << 16);
    g_W1frag[idx] = q;
}

// ---------------- kernel 1: PCEN + conv1 via warp mma + BN + ReLU + pool ----------------
// smem: fp32 img [64*65] | hi-even | hi-odd | lo-even | lo-odd (u16 x 4096 each) | BN
#define SM1_IMG 0
#define SM1_HE  16640
#define SM1_LE  33024
#define SM1_SC  49408
#define SM1_SH  49472
#define SM1_TOT 50816           // padded for harmless OOB reads of zero-weight taps
#define PL1 2048                // u32 per plane parity copy

__global__ __launch_bounds__(256) void conv1_pcen_kernel(
    const float* __restrict__ x,
    const float* __restrict__ log_s, const float* __restrict__ log_alpha,
    const float* __restrict__ log_delta, const float* __restrict__ log_r,
    const float* __restrict__ b1,
    const float* __restrict__ g,  const float* __restrict__ be,
    const float* __restrict__ mu, const float* __restrict__ va)
{
    extern __shared__ __align__(16) char smem[];
    float* img = (float*)(smem + SM1_IMG);
    u16* hE16 = (u16*)(smem + SM1_HE);
    u16* lE16 = (u16*)(smem + SM1_LE);
    const u32* pH = (const u32*)(smem + SM1_HE);
    const u32* pL = (const u32*)(smem + SM1_LE);
    float* scS = (float*)(smem + SM1_SC);
    float* shS = (float*)(smem + SM1_SH);

    const int b = blockIdx.x, t = threadIdx.x;
    const int w = t >> 5, lane = t & 31;
    const float* xb = x + (size_t)b * 4096;

    for (int i = t; i < 4096; i += 256)
        img[(i >> 6) * 65 + (i & 63)] = xb[i];
    if (t < 16) {
        if (t < C1) {
            float inv = g[t] * rsqrtf(va[t] + 1e-5f);
            scS[t] = inv;
            shS[t] = (b1[t] - mu[t]) * inv + be[t];
        } else { scS[t] = 0.f; shS[t] = 0.f; }
    }
    // per-warp conv1 B fragments
    uint4 qf[2][4];
    #pragma unroll
    for (int nt = 0; nt < 2; nt++)
        #pragma unroll
        for (int ks = 0; ks < 4; ks++)
            qf[nt][ks] = g_B1frag[(nt * 4 + ks) * 32 + lane];
    __syncthreads();

    // PCEN recurrence (thread t<64 owns row t)
    if (t < 64) {
        const float s     = expf(log_s[0]);
        const float alpha = expf(log_alpha[0]);
        const float delta = expf(log_delta[0]);
        const float r     = expf(log_r[0]);
        const float oms   = 1.0f - s;
        const float dr    = powf(delta, r);
        float* row = img + t * 65;
        float m = 0.0f;
        #pragma unroll 4
        for (int ww = 0; ww < 64; ww++) {
            float xv = row[ww];
            m = (ww == 0) ? s * xv : oms * m + s * xv;
            float Ma = __powf(m + 1e-6f, alpha);
            row[ww] = __powf(__fdividef(xv, Ma) + delta, r) - dr;
        }
    }
    __syncthreads();

    // plane build: hi/lo bf16, even + odd parity copies
    {
        u16* hO16 = hE16 + 4096;
        u16* lO16 = lE16 + 4096;
        for (int i = t; i < 4096; i += 256) {
            float v = img[(i >> 6) * 65 + (i & 63)];
            u16 h = bf16_bits(v);
            u16 l = bf16_bits(v - __uint_as_float((u32)h << 16));
            hE16[i] = h; lE16[i] = l;
            if (i > 0) { hO16[i - 1] = h; lO16[i - 1] = l; }
        }
        if (t == 0) { hO16[4095] = 0; lO16[4095] = 0; }
    }
    __syncthreads();

    const int r = lane >> 2;
    const int koff = (lane & 3) * 2;

    // m-tiles: 29 y-pairs x 8 x-octets = 232; tile = 2 rows x 8 cols
    for (int mt = w; mt < 232; mt += 8) {
        const int py = mt >> 3, xo = mt & 7;
        const int y0 = 2 * py, x0 = xo * 8;
        const int xbase = x0 + r + koff;

        float acc[2][4];
        #pragma unroll
        for (int nt = 0; nt < 2; nt++)
            { acc[nt][0]=0.f; acc[nt][1]=0.f; acc[nt][2]=0.f; acc[nt][3]=0.f; }

        #pragma unroll
        for (int ks = 0; ks < 4; ks++) {
            const int eA = (y0 + 2 * ks) * 64 + xbase;
            const int i0 = ((eA & 1) << 11) + (eA >> 1);
            u32 hA = pH[i0], hB = pH[i0 + 32], hC = pH[i0 + 64];
            u32 lA = pL[i0], lB = pL[i0 + 32], lC = pL[i0 + 64];
            #pragma unroll
            for (int nt = 0; nt < 2; nt++) {
                uint4 q = qf[nt][ks];
                mma_bf16(acc[nt], hA, hB, hB, hC, q.x, q.y);
                mma_bf16(acc[nt], hA, hB, hB, hC, q.z, q.w);
                mma_bf16(acc[nt], lA, lB, lB, lC, q.x, q.y);
            }
        }

        // BN + ReLU + 2x2 pool (vertical in-thread, horizontal via shfl)
        #pragma unroll
        for (int nt = 0; nt < 2; nt++) {
            int oc = nt * 8 + (lane & 3) * 2;
            float s0 = scS[oc], h0 = shS[oc];
            float s1 = scS[oc + 1], h1 = shS[oc + 1];
            float m0 = fmaxf(fmaxf(acc[nt][0] * s0 + h0, 0.f),
                             fmaxf(acc[nt][2] * s0 + h0, 0.f));
            float m1 = fmaxf(fmaxf(acc[nt][1] * s1 + h1, 0.f),
                             fmaxf(acc[nt][3] * s1 + h1, 0.f));
            m0 = fmaxf(m0, __shfl_xor_sync(0xFFFFFFFFu, m0, 4));
            m1 = fmaxf(m1, __shfl_xor_sync(0xFFFFFFFFu, m1, 4));
            if (!(r & 1)) {
                int px = (x0 + r) >> 1;
                if (px < P1) {
                    float* ob = g_p1 + (size_t)b * (C1 * P1 * IN2P) + py * IN2P + px;
                    if (oc < C1)     ob[oc * (P1 * IN2P)] = m0;
                    if (oc + 1 < C1) ob[(oc + 1) * (P1 * IN2P)] = m1;
                }
            }
        }
    }
}

// ---------------- kernel 2: conv2 via warp mma (bf16 k16, 3-term split) ----------------
#define PL_U32 6960
#define SM_PHE 0
#define SM_PLE 55680
#define SM_SC  111360
#define SM_SH  111488
#define SM_TOT2 111616

__global__ __launch_bounds__(256, 2) void conv2_mma_kernel(
    const float* __restrict__ b2,
    const float* __restrict__ g,  const float* __restrict__ be,
    const float* __restrict__ mu, const float* __restrict__ va)
{
    extern __shared__ __align__(16) char smem[];
    u16* hE16 = (u16*)(smem + SM_PHE);
    u16* lE16 = (u16*)(smem + SM_PLE);
    const u32* pH = (const u32*)(smem + SM_PHE);
    const u32* pL = (const u32*)(smem + SM_PLE);
    float* scS = (float*)(smem + SM_SC);
    float* shS = (float*)(smem + SM_SH);

    const int t = threadIdx.x, w = t >> 5, lane = t & 31;
    const int b = blockIdx.x;

    {
        const float* src = g_p1 + (size_t)b * 13920;
        u16* hO16 = hE16 + 13920;
        u16* lO16 = lE16 + 13920;
        for (int i = t; i < 13920; i += 256) {
            float v = src[i];
            u16 h = bf16_bits(v);
            u16 l = bf16_bits(v - __uint_as_float((u32)h << 16));
            hE16[i] = h; lE16[i] = l;
            if (i > 0) { hO16[i - 1] = h; lO16[i - 1] = l; }
        }
        if (t == 0) { hO16[13919] = 0; lO16[13919] = 0; }
    }
    if (t < C2) {
        float inv = g[t] * rsqrtf(va[t] + 1e-5f);
        scS[t] = inv;
        shS[t] = (b2[t] - mu[t]) * inv + be[t];
    }
    __syncthreads();

    int c0[4], c1[4];
    #pragma unroll
    for (int i = 0; i < 4; i++) {
        int mt = w * 4 + i; if (mt > 30) mt = 30;
        int p0 = mt * 16 + (lane >> 2); if (p0 > 483) p0 = 483;
        int p1 = p0 + 8;                if (p1 > 483) p1 = 483;
        int y0 = p0 / 22, x0 = p0 - y0 * 22;
        int y1 = p1 / 22, x1 = p1 - y1 * 22;
        int dx0 = (lane & 3) * 2;
        c0[i] = (x0 & 1) * PL_U32 + y0 * 16 + ((x0 + dx0 - (x0 & 1)) >> 1);
        c1[i] = (x1 & 1) * PL_U32 + y1 * 16 + ((x1 + dx0 - (x1 & 1)) >> 1);
    }

    float acc[4][4][4];
    #pragma unroll
    for (int i = 0; i < 4; i++)
        #pragma unroll
        for (int n = 0; n < 4; n++)
            { acc[i][n][0]=0.f; acc[i][n][1]=0.f; acc[i][n][2]=0.f; acc[i][n][3]=0.f; }

    const uint4* bfr = (const uint4*)g_Bfrag2;

    #pragma unroll 1
    for (int ic = 0; ic < 15; ic++) {
        #pragma unroll 1
        for (int dyp = 0; dyp < 4; dyp++) {
            const int ks = ic * 4 + dyp;
            uint4 q0 = bfr[(ks * 4 + 0) * 32 + lane];
            uint4 q1 = bfr[(ks * 4 + 1) * 32 + lane];
            uint4 q2 = bfr[(ks * 4 + 2) * 32 + lane];
            uint4 q3 = bfr[(ks * 4 + 3) * 32 + lane];
            const int kb0 = (ic * 29 + dyp * 2) * 16;
            const int kb1 = kb0 + 16;
            #pragma unroll
            for (int i = 0; i < 4; i++) {
                u32 ah0 = pH[c0[i] + kb0], ah1 = pH[c1[i] + kb0];
                u32 ah2 = pH[c0[i] + kb1], ah3 = pH[c1[i] + kb1];
                u32 al0 = pL[c0[i] + kb0], al1 = pL[c1[i] + kb0];
                u32 al2 = pL[c0[i] + kb1], al3 = pL[c1[i] + kb1];
                mma_bf16(acc[i][0], ah0, ah1, ah2, ah3, q0.x, q0.y);
                mma_bf16(acc[i][0], ah0, ah1, ah2, ah3, q0.z, q0.w);
                mma_bf16(acc[i][0], al0, al1, al2, al3, q0.x, q0.y);
                mma_bf16(acc[i][1], ah0, ah1, ah2, ah3, q1.x, q1.y);
                mma_bf16(acc[i][1], ah0, ah1, ah2, ah3, q1.z, q1.w);
                mma_bf16(acc[i][1], al0, al1, al2, al3, q1.x, q1.y);
                mma_bf16(acc[i][2], ah0, ah1, ah2, ah3, q2.x, q2.y);
                mma_bf16(acc[i][2], ah0, ah1, ah2, ah3, q2.z, q2.w);
                mma_bf16(acc[i][2], al0, al1, al2, al3, q2.x, q2.y);
                mma_bf16(acc[i][3], ah0, ah1, ah2, ah3, q3.x, q3.y);
                mma_bf16(acc[i][3], ah0, ah1, ah2, ah3, q3.z, q3.w);
                mma_bf16(acc[i][3], al0, al1, al2, al3, q3.x, q3.y);
            }
        }
    }

    __syncthreads();
    float* stg = (float*)smem;             // [484][33]
    #pragma unroll
    for (int i = 0; i < 4; i++) {
        int mt = w * 4 + i; if (mt > 30) mt = 30;
        int r0 = mt * 16 + (lane >> 2), r1 = r0 + 8;
        #pragma unroll
        for (int n = 0; n < 4; n++) {
            int oc = n * 8 + (lane & 3) * 2;
            if (oc < C2) {
                float s0 = scS[oc], h0 = shS[oc];
                float s1 = scS[oc + 1], h1 = shS[oc + 1];
                if (r0 < 484) {
                    stg[r0 * 33 + oc]     = fmaxf(acc[i][n][0] * s0 + h0, 0.f);
                    stg[r0 * 33 + oc + 1] = fmaxf(acc[i][n][1] * s1 + h1, 0.f);
                }
                if (r1 < 484) {
                    stg[r1 * 33 + oc]     = fmaxf(acc[i][n][2] * s0 + h0, 0.f);
                    stg[r1 * 33 + oc + 1] = fmaxf(acc[i][n][3] * s1 + h1, 0.f);
                }
            }
        }
    }
    __syncthreads();
    for (int i = t; i < 3630; i += 256) {
        int oc = i / 121, pos = i % 121;
        int py = pos / 11, px = pos % 11;
        int p00 = (2 * py) * 22 + 2 * px;
        float v = fmaxf(fmaxf(stg[p00 * 33 + oc], stg[(p00 + 1) * 33 + oc]),
                        fmaxf(stg[(p00 + 22) * 33 + oc], stg[(p00 + 23) * 33 + oc]));
        u16 h = bf16_bits(v);
        u16 l = bf16_bits(v - __uint_as_float((u32)h << 16));
        g_p2h[(size_t)b * FC1_IN + i] = h;
        g_p2l[(size_t)b * FC1_IN + i] = l;
    }
}

// ---------------- kernel 3: FC1 via warp mma (bf16, 3-term, K-split 8) ----------------
__global__ __launch_bounds__(256, 1) void fc1_mma_kernel()
{
    const int t = threadIdx.x, w = t >> 5, lane = t & 31;
    const int mt = blockIdx.x;
    const int kz = blockIdx.y;

    const int row0 = mt * 128 + w * 16 + (lane >> 2);
    const size_t base0 = (size_t)row0 * FC1_IN;
    const size_t base1 = (size_t)(row0 + 8) * FC1_IN;
    const int koff = (lane & 3) * 2;

    const int ks0 = kz * 28 + (kz < 3 ? kz : 3);
    const int nks = 28 + (kz < 3 ? 1 : 0);

    float acc[25][4];
    #pragma unroll
    for (int n = 0; n < 25; n++)
        { acc[n][0]=0.f; acc[n][1]=0.f; acc[n][2]=0.f; acc[n][3]=0.f; }

    #pragma unroll 1
    for (int ks = ks0; ks < ks0 + nks; ks++) {
        const int k0 = ks * 16 + koff;
        u32 ah0 = *(const u32*)&g_p2h[base0 + k0];
        u32 ah1 = *(const u32*)&g_p2h[base1 + k0];
        u32 ah2 = *(const u32*)&g_p2h[base0 + k0 + 8];
        u32 ah3 = *(const u32*)&g_p2h[base1 + k0 + 8];
        u32 al0 = *(const u32*)&g_p2l[base0 + k0];
        u32 al1 = *(const u32*)&g_p2l[base1 + k0];
        u32 al2 = *(const u32*)&g_p2l[base0 + k0 + 8];
        u32 al3 = *(const u32*)&g_p2l[base1 + k0 + 8];
        const uint4* bp = &g_W1frag[(size_t)ks * 25 * 32 + lane];
        #pragma unroll
        for (int n = 0; n < 25; n++) {
            uint4 q = bp[n * 32];
            mma_bf16(acc[n], ah0, ah1, ah2, ah3, q.x, q.y);
            mma_bf16(acc[n], ah0, ah1, ah2, ah3, q.z, q.w);
            mma_bf16(acc[n], al0, al1, al2, al3, q.x, q.y);
        }
    }

    float* dst = g_fc1p + (size_t)kz * B * FC1_OUT;
    const int r0 = mt * 128 + w * 16 + (lane >> 2);
    const int r1 = r0 + 8;
    #pragma unroll
    for (int n = 0; n < 25; n++) {
        int o = n * 8 + (lane & 3) * 2;
        dst[(size_t)r0 * FC1_OUT + o]     = acc[n][0];
        dst[(size_t)r0 * FC1_OUT + o + 1] = acc[n][1];
        dst[(size_t)r1 * FC1_OUT + o]     = acc[n][2];
        dst[(size_t)r1 * FC1_OUT + o + 1] = acc[n][3];
    }
}

// ---------------- kernel 4: FC2 + sigmoid ----------------
__global__ __launch_bounds__(256) void fc2_kernel(
    const float* __restrict__ fc1b,
    const float* __restrict__ w2, const float* __restrict__ b2,
    float* __restrict__ out)
{
    const int warp = threadIdx.x >> 5, lane = threadIdx.x & 31;
    const int b = blockIdx.x * 8 + warp;
    const size_t PS = (size_t)B * FC1_OUT;
    const float* base = g_fc1p + (size_t)b * FC1_OUT;
    float s0 = 0.f, s1 = 0.f;
    for (int o = lane; o < FC1_OUT; o += 32) {
        float v = fc1b[o];
        #pragma unroll
        for (int p = 0; p < KSPLIT; p++)
            v += base[p * PS + o];
        v = fmaxf(v, 0.f);
        s0 += v * w2[o];
        s1 += v * w2[FC1_OUT + o];
    }
    #pragma unroll
    for (int d = 16; d > 0; d >>= 1) {
        s0 += __shfl_xor_sync(0xFFFFFFFFu, s0, d);
        s1 += __shfl_xor_sync(0xFFFFFFFFu, s1, d);
    }
    if (lane == 0) {
        out[2 * b + 0] = 1.f / (1.f + expf(-(s0 + b2[0])));
        out[2 * b + 1] = 1.f / (1.f + expf(-(s1 + b2[1])));
    }
}

// ---------------- launch ----------------
extern "C" void kernel_launch(void* const* d_in, const int* in_sizes, int n_in,
                              void* d_out, int out_size)
{
    const float* x       = (const float*)d_in[0];
    const float* log_s   = (const float*)d_in[1];
    const float* log_a   = (const float*)d_in[2];
    const float* log_d   = (const float*)d_in[3];
    const float* log_r   = (const float*)d_in[4];
    const float* conv1_w = (const float*)d_in[5];
    const float* conv1_b = (const float*)d_in[6];
    const float* bn1_g   = (const float*)d_in[7];
    const float* bn1_b   = (const float*)d_in[8];
    const float* bn1_m   = (const float*)d_in[9];
    const float* bn1_v   = (const float*)d_in[10];
    const float* conv2_w = (const float*)d_in[11];
    const float* conv2_b = (const float*)d_in[12];
    const float* bn2_g   = (const float*)d_in[13];
    const float* bn2_b   = (const float*)d_in[14];
    const float* bn2_m   = (const float*)d_in[15];
    const float* bn2_v   = (const float*)d_in[16];
    const float* fc1_w   = (const float*)d_in[17];
    const float* fc1_b   = (const float*)d_in[18];
    const float* fc2_w   = (const float*)d_in[19];
    const float* fc2_b   = (const float*)d_in[20];
    float* out = (float*)d_out;

    static int smem_set = 0;
    if (!smem_set) {
        cudaFuncSetAttribute(conv2_mma_kernel,
                             cudaFuncAttributeMaxDynamicSharedMemorySize, SM_TOT2);
        cudaFuncSetAttribute(conv1_pcen_kernel,
                             cudaFuncAttributeMaxDynamicSharedMemorySize, SM1_TOT);
        smem_set = 1;
    }

    prep_b_frag<<<30, 256>>>(conv2_w);
    prep_b1_frag<<<1, 256>>>(conv1_w);
    prep_w1_frag<<<(NKS1 * 25 * 32 + 255) / 256, 256>>>(fc1_w);
    conv1_pcen_kernel<<<B, 256, SM1_TOT>>>(x, log_s, log_a, log_d, log_r,
                                           conv1_b, bn1_g, bn1_b, bn1_m, bn1_v);
    conv2_mma_kernel<<<B, 256, SM_TOT2>>>(conv2_b, bn2_g, bn2_b, bn2_m, bn2_v);
    fc1_mma_kernel<<<dim3(16, KSPLIT), 256>>>();
    fc2_kernel<<<B / 8, 256>>>(fc1_b, fc2_w, fc2_b, out);
}

// round 11
// speedup vs baseline: 1.4997x; 1.4997x over previous
#include <cuda_runtime.h>
#include <cuda_fp16.h>
#include <math.h>
#include <stdint.h>

#define B 2048
#define C1 15
#define C2 30
#define P1 29
#define P2 11
#define IN2P 32
#define FC1_IN (30*11*11)
#define FC1_OUT 200
#define KSPLIT 8
#define NKS1 227              // ceil(3630/16)
#define NKS2 53               // ceil(105/2) conv2 row-pair k-steps

typedef uint16_t u16;
typedef uint32_t u32;

// ---------------- warp mma m16n8k16 fp16 -> f32 ----------------
__device__ __forceinline__ void mma_f16(float* d, u32 a0, u32 a1, u32 a2, u32 a3,
                                        u32 b0, u32 b1) {
    asm volatile(
        "mma.sync.aligned.m16n8k16.row.col.f32.f16.f16.f32 "
        "{%0,%1,%2,%3}, {%4,%5,%6,%7}, {%8,%9}, {%0,%1,%2,%3};"
        : "+f"(d[0]), "+f"(d[1]), "+f"(d[2]), "+f"(d[3])
        : "r"(a0), "r"(a1), "r"(a2), "r"(a3), "r"(b0), "r"(b1));
}

__device__ __forceinline__ u16 f16_bits(float v) {
    return __half_as_ushort(__float2half(v));
}
__device__ __forceinline__ float f16_val(u16 b) {
    return __half2float(__ushort_as_half(b));
}

// ---------------- scratch ----------------
__device__ float g_fc1p[KSPLIT * B * FC1_OUT];
__device__ __align__(4)  u16  g_p1h[B * C1 * P1 * IN2P];        // conv1 out, fp16
__device__ __align__(4)  u16  g_p2h[B * FC1_IN + 64];           // conv2 out, fp16
__device__ __align__(16) uint4 g_Bfrag2[NKS2 * 4 * 32];         // conv2 W frags
__device__ __align__(16) uint4 g_B1frag[2 * 4 * 32];            // conv1 W frags
__device__ __align__(16) uint4 g_W1frag[NKS1 * 25 * 32];        // fc1 W frags

// ---------------- kernel 0a: prep conv2 W fragments (row-pair packed) ----------------
__global__ void prep_b_frag(const float* __restrict__ w2)
{
    int idx = blockIdx.x * 256 + threadIdx.x;    // ks*128 + nt*32 + lane
    if (idx >= NKS2 * 128) return;
    int lane = idx & 31, nt = (idx >> 5) & 3, ks = idx >> 7;
    int oc = nt * 8 + (lane >> 2), k0 = (lane & 3) * 2;
    int rA = 2 * ks, rB = rA + 1;

    float v[4] = {0.f, 0.f, 0.f, 0.f};
    if (oc < C2) {
        int icA = rA / 7, dyA = rA % 7;
        const float* wa = w2 + ((oc * C1 + icA) * 7 + dyA) * 7;
        v[0] = wa[k0];
        if (k0 + 1 < 7) v[1] = wa[k0 + 1];
        if (rB <= 104) {
            int icB = rB / 7, dyB = rB % 7;
            const float* wb = w2 + ((oc * C1 + icB) * 7 + dyB) * 7;
            v[2] = wb[k0];
            if (k0 + 1 < 7) v[3] = wb[k0 + 1];
        }
    }
    u16 h[4], l[4];
    #pragma unroll
    for (int i = 0; i < 4; i++) {
        h[i] = f16_bits(v[i]);
        l[i] = f16_bits(v[i] - f16_val(h[i]));
    }
    uint4 q;
    q.x = (u32)h[0] | ((u32)h[1] << 16);
    q.y = (u32)h[2] | ((u32)h[3] << 16);
    q.z = (u32)l[0] | ((u32)l[1] << 16);
    q.w = (u32)l[2] | ((u32)l[3] << 16);
    g_Bfrag2[idx] = q;
}

// ---------------- kernel 0b: prep conv1 W fragments ----------------
__global__ void prep_b1_frag(const float* __restrict__ w1)
{
    int idx = threadIdx.x;               // 256 threads
    int lane = idx & 31, ks = (idx >> 5) & 3, nt = idx >> 7;
    int oc = nt * 8 + (lane >> 2), k0 = (lane & 3) * 2;
    int dy0 = ks * 2, dy1 = dy0 + 1;

    float v[4] = {0.f, 0.f, 0.f, 0.f};
    if (oc < C1) {
        const float* wb = w1 + oc * 49;
        v[0] = wb[dy0 * 7 + k0];
        if (k0 + 1 < 7) v[1] = wb[dy0 * 7 + k0 + 1];
        if (dy1 < 7) {
            v[2] = wb[dy1 * 7 + k0];
            if (k0 + 1 < 7) v[3] = wb[dy1 * 7 + k0 + 1];
        }
    }
    u16 h[4], l[4];
    #pragma unroll
    for (int i = 0; i < 4; i++) {
        h[i] = f16_bits(v[i]);
        l[i] = f16_bits(v[i] - f16_val(h[i]));
    }
    uint4 q;
    q.x = (u32)h[0] | ((u32)h[1] << 16);
    q.y = (u32)h[2] | ((u32)h[3] << 16);
    q.z = (u32)l[0] | ((u32)l[1] << 16);
    q.w = (u32)l[2] | ((u32)l[3] << 16);
    g_B1frag[(nt * 4 + ks) * 32 + lane] = q;
}

// ---------------- kernel 0c: prep fc1 W fragments ----------------
__global__ void prep_w1_frag(const float* __restrict__ w)
{
    int idx = blockIdx.x * 256 + threadIdx.x;
    if (idx >= NKS1 * 25 * 32) return;
    int lane = idx & 31;
    int nt = (idx >> 5) % 25;
    int ks = idx / (25 * 32);
    int o = nt * 8 + (lane >> 2);
    int k0 = ks * 16 + (lane & 3) * 2;
    const float* wr = w + (size_t)o * FC1_IN;

    float v[4];
    v[0] = (k0     < FC1_IN) ? wr[k0]     : 0.f;
    v[1] = (k0 + 1 < FC1_IN) ? wr[k0 + 1] : 0.f;
    v[2] = (k0 + 8 < FC1_IN) ? wr[k0 + 8] : 0.f;
    v[3] = (k0 + 9 < FC1_IN) ? wr[k0 + 9] : 0.f;
    u16 h[4], l[4];
    #pragma unroll
    for (int i = 0; i < 4; i++) {
        h[i] = f16_bits(v[i]);
        l[i] = f16_bits(v[i] - f16_val(h[i]));
    }
    uint4 q;
    q.x = (u32)h[0] | ((u32)h[1] << 16);
    q.y = (u32)h[2] | ((u32)h[3] << 16);
    q.z = (u32)l[0] | ((u32)l[1] << 16);
    q.w = (u32)l[2] | ((u32)l[3] << 16);
    g_W1frag[idx] = q;
}

// ---------------- kernel 1: PCEN + conv1 (fp16 mma) + BN + ReLU + pool ----------------
// smem: fp32 img [64*65] | hi-even [4224 u16] | hi-odd [4224 u16] | BN
#define PL1 2112                 // u32 per parity copy (66 rows, zero tail)
#define SM1_IMG 0
#define SM1_HE  16640            // 2*4224*2 = 16896 bytes
#define SM1_SC  33536
#define SM1_SH  33600
#define SM1_TOT 33664

__global__ __launch_bounds__(256) void conv1_pcen_kernel(
    const float* __restrict__ x,
    const float* __restrict__ log_s, const float* __restrict__ log_alpha,
    const float* __restrict__ log_delta, const float* __restrict__ log_r,
    const float* __restrict__ b1,
    const float* __restrict__ g,  const float* __restrict__ be,
    const float* __restrict__ mu, const float* __restrict__ va)
{
    extern __shared__ __align__(16) char smem[];
    float* img = (float*)(smem + SM1_IMG);
    u16* hE16 = (u16*)(smem + SM1_HE);
    const u32* pH = (const u32*)(smem + SM1_HE);
    float* scS = (float*)(smem + SM1_SC);
    float* shS = (float*)(smem + SM1_SH);

    const int b = blockIdx.x, t = threadIdx.x;
    const int w = t >> 5, lane = t & 31;
    const float* xb = x + (size_t)b * 4096;

    for (int i = t; i < 4096; i += 256)
        img[(i >> 6) * 65 + (i & 63)] = xb[i];
    if (t < 16) {
        if (t < C1) {
            float inv = g[t] * rsqrtf(va[t] + 1e-5f);
            scS[t] = inv;
            shS[t] = (b1[t] - mu[t]) * inv + be[t];
        } else { scS[t] = 0.f; shS[t] = 0.f; }
    }
    uint4 qf[2][4];
    #pragma unroll
    for (int nt = 0; nt < 2; nt++)
        #pragma unroll
        for (int ks = 0; ks < 4; ks++)
            qf[nt][ks] = g_B1frag[(nt * 4 + ks) * 32 + lane];
    __syncthreads();

    // PCEN recurrence
    if (t < 64) {
        const float s     = expf(log_s[0]);
        const float alpha = expf(log_alpha[0]);
        const float delta = expf(log_delta[0]);
        const float r     = expf(log_r[0]);
        const float oms   = 1.0f - s;
        const float dr    = powf(delta, r);
        float* row = img + t * 65;
        float m = 0.0f;
        #pragma unroll 4
        for (int ww = 0; ww < 64; ww++) {
            float xv = row[ww];
            m = (ww == 0) ? s * xv : oms * m + s * xv;
            float Ma = __powf(m + 1e-6f, alpha);
            row[ww] = __powf(__fdividef(xv, Ma) + delta, r) - dr;
        }
    }
    __syncthreads();

    // hi plane build, even + odd parity copies, zero tail rows 64..65
    {
        u16* hO16 = hE16 + 4224;
        for (int i = t; i < 4224; i += 256) {
            u16 h = 0;
            if (i < 4096) h = f16_bits(img[(i >> 6) * 65 + (i & 63)]);
            hE16[i] = h;
            if (i > 0) hO16[i - 1] = h;
        }
        if (t == 0) hO16[4223] = 0;
    }
    __syncthreads();

    const int r = lane >> 2;
    const int koff = (lane & 3) * 2;

    for (int mt = w; mt < 232; mt += 8) {
        const int py = mt >> 3, xo = mt & 7;
        const int y0 = 2 * py, x0 = xo * 8;
        const int eA = y0 * 64 + x0 + r + koff;
        int i0 = (eA & 1) * PL1 + (eA >> 1);

        float acc[2][4];
        #pragma unroll
        for (int nt = 0; nt < 2; nt++)
            { acc[nt][0]=0.f; acc[nt][1]=0.f; acc[nt][2]=0.f; acc[nt][3]=0.f; }

        u32 hA = pH[i0];
        #pragma unroll
        for (int ks = 0; ks < 4; ks++) {
            u32 hB = pH[i0 + 32];
            u32 hC = pH[i0 + 64];
            #pragma unroll
            for (int nt = 0; nt < 2; nt++) {
                uint4 q = qf[nt][ks];
                mma_f16(acc[nt], hA, hB, hB, hC, q.x, q.y);
                mma_f16(acc[nt], hA, hB, hB, hC, q.z, q.w);
            }
            hA = hC;
            i0 += 64;
        }

        #pragma unroll
        for (int nt = 0; nt < 2; nt++) {
            int oc = nt * 8 + (lane & 3) * 2;
            float s0 = scS[oc], h0 = shS[oc];
            float s1 = scS[oc + 1], h1 = shS[oc + 1];
            float m0 = fmaxf(fmaxf(acc[nt][0] * s0 + h0, 0.f),
                             fmaxf(acc[nt][2] * s0 + h0, 0.f));
            float m1 = fmaxf(fmaxf(acc[nt][1] * s1 + h1, 0.f),
                             fmaxf(acc[nt][3] * s1 + h1, 0.f));
            m0 = fmaxf(m0, __shfl_xor_sync(0xFFFFFFFFu, m0, 4));
            m1 = fmaxf(m1, __shfl_xor_sync(0xFFFFFFFFu, m1, 4));
            if (!(r & 1)) {
                int px = (x0 + r) >> 1;
                if (px < P1) {
                    u16* ob = g_p1h + (size_t)b * (C1 * P1 * IN2P) + py * IN2P + px;
                    if (oc < C1)     ob[oc * (P1 * IN2P)] = f16_bits(m0);
                    if (oc + 1 < C1) ob[(oc + 1) * (P1 * IN2P)] = f16_bits(m1);
                }
            }
        }
    }
}

// ---------------- kernel 2: conv2 via fp16 mma (2-term, row-pair K) ----------------
#define PL_U32 6960
#define SM_SC  63888            // stage [484][33] f32 overlays planes
#define SM_SH  64016
#define SM_RT  64144            // rowTab[106]
#define SM_TOT2 64576

__global__ __launch_bounds__(256, 2) void conv2_mma_kernel(
    const float* __restrict__ b2,
    const float* __restrict__ g,  const float* __restrict__ be,
    const float* __restrict__ mu, const float* __restrict__ va)
{
    extern __shared__ __align__(16) char smem[];
    u16* hE16 = (u16*)smem;
    const u32* pH = (const u32*)smem;
    float* scS = (float*)(smem + SM_SC);
    float* shS = (float*)(smem + SM_SH);
    int* rowTab = (int*)(smem + SM_RT);

    const int t = threadIdx.x, w = t >> 5, lane = t & 31;
    const int b = blockIdx.x;

    // hi plane build (pure u16 copies of conv1's fp16 output)
    {
        const u16* src = g_p1h + (size_t)b * 13920;
        u16* hO16 = hE16 + 13920;
        for (int i = t; i < 13920; i += 256) {
            u16 h = src[i];
            hE16[i] = h;
            if (i > 0) hO16[i - 1] = h;
        }
        if (t == 0) hO16[13919] = 0;
    }
    if (t < C2) {
        float inv = g[t] * rsqrtf(va[t] + 1e-5f);
        scS[t] = inv;
        shS[t] = (b2[t] - mu[t]) * inv + be[t];
    }
    if (t < 106) {
        int r = (t < 105) ? t : 104;
        rowTab[t] = ((r / 7) * 29 + (r % 7)) * 16;
    }
    __syncthreads();

    int c0[4], c1[4];
    #pragma unroll
    for (int i = 0; i < 4; i++) {
        int mt = w * 4 + i; if (mt > 30) mt = 30;
        int p0 = mt * 16 + (lane >> 2); if (p0 > 483) p0 = 483;
        int p1 = p0 + 8;                if (p1 > 483) p1 = 483;
        int y0 = p0 / 22, x0 = p0 - y0 * 22;
        int y1 = p1 / 22, x1 = p1 - y1 * 22;
        int dx0 = (lane & 3) * 2;
        c0[i] = (x0 & 1) * PL_U32 + y0 * 16 + ((x0 + dx0 - (x0 & 1)) >> 1);
        c1[i] = (x1 & 1) * PL_U32 + y1 * 16 + ((x1 + dx0 - (x1 & 1)) >> 1);
    }

    float acc[4][4][4];
    #pragma unroll
    for (int i = 0; i < 4; i++)
        #pragma unroll
        for (int n = 0; n < 4; n++)
            { acc[i][n][0]=0.f; acc[i][n][1]=0.f; acc[i][n][2]=0.f; acc[i][n][3]=0.f; }

    #pragma unroll 1
    for (int j = 0; j < NKS2; j++) {
        const int kb0 = rowTab[2 * j];
        const int kb1 = rowTab[2 * j + 1];
        uint4 q0 = g_Bfrag2[(j * 4 + 0) * 32 + lane];
        uint4 q1 = g_Bfrag2[(j * 4 + 1) * 32 + lane];
        uint4 q2 = g_Bfrag2[(j * 4 + 2) * 32 + lane];
        uint4 q3 = g_Bfrag2[(j * 4 + 3) * 32 + lane];
        #pragma unroll
        for (int i = 0; i < 4; i++) {
            u32 ah0 = pH[c0[i] + kb0], ah1 = pH[c1[i] + kb0];
            u32 ah2 = pH[c0[i] + kb1], ah3 = pH[c1[i] + kb1];
            mma_f16(acc[i][0], ah0, ah1, ah2, ah3, q0.x, q0.y);
            mma_f16(acc[i][0], ah0, ah1, ah2, ah3, q0.z, q0.w);
            mma_f16(acc[i][1], ah0, ah1, ah2, ah3, q1.x, q1.y);
            mma_f16(acc[i][1], ah0, ah1, ah2, ah3, q1.z, q1.w);
            mma_f16(acc[i][2], ah0, ah1, ah2, ah3, q2.x, q2.y);
            mma_f16(acc[i][2], ah0, ah1, ah2, ah3, q2.z, q2.w);
            mma_f16(acc[i][3], ah0, ah1, ah2, ah3, q3.x, q3.y);
            mma_f16(acc[i][3], ah0, ah1, ah2, ah3, q3.z, q3.w);
        }
    }

    __syncthreads();                       // planes dead; reuse as stage
    float* stg = (float*)smem;             // [484][33]
    #pragma unroll
    for (int i = 0; i < 4; i++) {
        int mt = w * 4 + i; if (mt > 30) mt = 30;
        int r0 = mt * 16 + (lane >> 2), r1 = r0 + 8;
        #pragma unroll
        for (int n = 0; n < 4; n++) {
            int oc = n * 8 + (lane & 3) * 2;
            if (oc < C2) {
                float s0 = scS[oc], h0 = shS[oc];
                float s1 = scS[oc + 1], h1 = shS[oc + 1];
                if (r0 < 484) {
                    stg[r0 * 33 + oc]     = fmaxf(acc[i][n][0] * s0 + h0, 0.f);
                    stg[r0 * 33 + oc + 1] = fmaxf(acc[i][n][1] * s1 + h1, 0.f);
                }
                if (r1 < 484) {
                    stg[r1 * 33 + oc]     = fmaxf(acc[i][n][2] * s0 + h0, 0.f);
                    stg[r1 * 33 + oc + 1] = fmaxf(acc[i][n][3] * s1 + h1, 0.f);
                }
            }
        }
    }
    __syncthreads();
    for (int i = t; i < 3630; i += 256) {
        int oc = i / 121, pos = i % 121;
        int py = pos / 11, px = pos % 11;
        int p00 = (2 * py) * 22 + 2 * px;
        float v = fmaxf(fmaxf(stg[p00 * 33 + oc], stg[(p00 + 1) * 33 + oc]),
                        fmaxf(stg[(p00 + 22) * 33 + oc], stg[(p00 + 23) * 33 + oc]));
        g_p2h[(size_t)b * FC1_IN + i] = f16_bits(v);
    }
}

// ---------------- kernel 3: FC1 via fp16 mma (2-term, K-split 8) ----------------
__global__ __launch_bounds__(256, 1) void fc1_mma_kernel()
{
    const int t = threadIdx.x, w = t >> 5, lane = t & 31;
    const int mt = blockIdx.x;
    const int kz = blockIdx.y;

    const int row0 = mt * 128 + w * 16 + (lane >> 2);
    const size_t base0 = (size_t)row0 * FC1_IN;
    const size_t base1 = (size_t)(row0 + 8) * FC1_IN;
    const int koff = (lane & 3) * 2;

    const int ks0 = kz * 28 + (kz < 3 ? kz : 3);
    const int nks = 28 + (kz < 3 ? 1 : 0);

    float acc[25][4];
    #pragma unroll
    for (int n = 0; n < 25; n++)
        { acc[n][0]=0.f; acc[n][1]=0.f; acc[n][2]=0.f; acc[n][3]=0.f; }

    #pragma unroll 1
    for (int ks = ks0; ks < ks0 + nks; ks++) {
        const int k0 = ks * 16 + koff;
        u32 ah0 = *(const u32*)&g_p2h[base0 + k0];
        u32 ah1 = *(const u32*)&g_p2h[base1 + k0];
        u32 ah2 = *(const u32*)&g_p2h[base0 + k0 + 8];
        u32 ah3 = *(const u32*)&g_p2h[base1 + k0 + 8];
        const uint4* bp = &g_W1frag[(size_t)ks * 25 * 32 + lane];
        #pragma unroll
        for (int n = 0; n < 25; n++) {
            uint4 q = bp[n * 32];
            mma_f16(acc[n], ah0, ah1, ah2, ah3, q.x, q.y);
            mma_f16(acc[n], ah0, ah1, ah2, ah3, q.z, q.w);
        }
    }

    float* dst = g_fc1p + (size_t)kz * B * FC1_OUT;
    const int r0 = row0, r1 = row0 + 8;
    #pragma unroll
    for (int n = 0; n < 25; n++) {
        int o = n * 8 + (lane & 3) * 2;
        dst[(size_t)r0 * FC1_OUT + o]     = acc[n][0];
        dst[(size_t)r0 * FC1_OUT + o + 1] = acc[n][1];
        dst[(size_t)r1 * FC1_OUT + o]     = acc[n][2];
        dst[(size_t)r1 * FC1_OUT + o + 1] = acc[n][3];
    }
}

// ---------------- kernel 4: FC2 + sigmoid ----------------
__global__ __launch_bounds__(256) void fc2_kernel(
    const float* __restrict__ fc1b,
    const float* __restrict__ w2, const float* __restrict__ b2,
    float* __restrict__ out)
{
    const int warp = threadIdx.x >> 5, lane = threadIdx.x & 31;
    const int b = blockIdx.x * 8 + warp;
    const size_t PS = (size_t)B * FC1_OUT;
    const float* base = g_fc1p + (size_t)b * FC1_OUT;
    float s0 = 0.f, s1 = 0.f;
    for (int o = lane; o < FC1_OUT; o += 32) {
        float v = fc1b[o];
        #pragma unroll
        for (int p = 0; p < KSPLIT; p++)
            v += base[p * PS + o];
        v = fmaxf(v, 0.f);
        s0 += v * w2[o];
        s1 += v * w2[FC1_OUT + o];
    }
    #pragma unroll
    for (int d = 16; d > 0; d >>= 1) {
        s0 += __shfl_xor_sync(0xFFFFFFFFu, s0, d);
        s1 += __shfl_xor_sync(0xFFFFFFFFu, s1, d);
    }
    if (lane == 0) {
        out[2 * b + 0] = 1.f / (1.f + expf(-(s0 + b2[0])));
        out[2 * b + 1] = 1.f / (1.f + expf(-(s1 + b2[1])));
    }
}

// ---------------- launch ----------------
extern "C" void kernel_launch(void* const* d_in, const int* in_sizes, int n_in,
                              void* d_out, int out_size)
{
    const float* x       = (const float*)d_in[0];
    const float* log_s   = (const float*)d_in[1];
    const float* log_a   = (const float*)d_in[2];
    const float* log_d   = (const float*)d_in[3];
    const float* log_r   = (const float*)d_in[4];
    const float* conv1_w = (const float*)d_in[5];
    const float* conv1_b = (const float*)d_in[6];
    const float* bn1_g   = (const float*)d_in[7];
    const float* bn1_b   = (const float*)d_in[8];
    const float* bn1_m   = (const float*)d_in[9];
    const float* bn1_v   = (const float*)d_in[10];
    const float* conv2_w = (const float*)d_in[11];
    const float* conv2_b = (const float*)d_in[12];
    const float* bn2_g   = (const float*)d_in[13];
    const float* bn2_b   = (const float*)d_in[14];
    const float* bn2_m   = (const float*)d_in[15];
    const float* bn2_v   = (const float*)d_in[16];
    const float* fc1_w   = (const float*)d_in[17];
    const float* fc1_b   = (const float*)d_in[18];
    const float* fc2_w   = (const float*)d_in[19];
    const float* fc2_b   = (const float*)d_in[20];
    float* out = (float*)d_out;

    static int smem_set = 0;
    if (!smem_set) {
        cudaFuncSetAttribute(conv2_mma_kernel,
                             cudaFuncAttributeMaxDynamicSharedMemorySize, SM_TOT2);
        cudaFuncSetAttribute(conv1_pcen_kernel,
                             cudaFuncAttributeMaxDynamicSharedMemorySize, SM1_TOT);
        smem_set = 1;
    }

    prep_b_frag<<<(NKS2 * 128 + 255) / 256, 256>>>(conv2_w);
    prep_b1_frag<<<1, 256>>>(conv1_w);
    prep_w1_frag<<<(NKS1 * 25 * 32 + 255) / 256, 256>>>(fc1_w);
    conv1_pcen_kernel<<<B, 256, SM1_TOT>>>(x, log_s, log_a, log_d, log_r,
                                           conv1_b, bn1_g, bn1_b, bn1_m, bn1_v);
    conv2_mma_kernel<<<B, 256, SM_TOT2>>>(conv2_b, bn2_g, bn2_b, bn2_m, bn2_v);
    fc1_mma_kernel<<<dim3(16, KSPLIT), 256>>>();
    fc2_kernel<<<B / 8, 256>>>(fc1_b, fc2_w, fc2_b, out);
}

// round 12
// speedup vs baseline: 1.9100x; 1.2736x over previous
#include <cuda_runtime.h>
#include <cuda_fp16.h>
#include <math.h>
#include <stdint.h>

#define B 2048
#define C1 15
#define C2 30
#define P1 29
#define P2 11
#define IN2P 32
#define FC1_IN (30*11*11)
#define FC1_OUT 200
#define KSPLIT 8
#define NKS1 227              // ceil(3630/16)
#define NKS2 53               // ceil(105/2) conv2 row-pair k-steps

typedef uint16_t u16;
typedef uint32_t u32;

// ---------------- warp mma m16n8k16 fp16 -> f32 ----------------
__device__ __forceinline__ void mma_f16(float* d, u32 a0, u32 a1, u32 a2, u32 a3,
                                        u32 b0, u32 b1) {
    asm volatile(
        "mma.sync.aligned.m16n8k16.row.col.f32.f16.f16.f32 "
        "{%0,%1,%2,%3}, {%4,%5,%6,%7}, {%8,%9}, {%0,%1,%2,%3};"
        : "+f"(d[0]), "+f"(d[1]), "+f"(d[2]), "+f"(d[3])
        : "r"(a0), "r"(a1), "r"(a2), "r"(a3), "r"(b0), "r"(b1));
}

__device__ __forceinline__ u16 f16_bits(float v) {
    return __half_as_ushort(__float2half(v));
}

// ---------------- scratch ----------------
__device__ float g_fc1p[KSPLIT * B * FC1_OUT];
__device__ __align__(4)  u16  g_p1h[B * C1 * P1 * IN2P];        // conv1 out, fp16
__device__ __align__(4)  u16  g_p2h[B * FC1_IN + 64];           // conv2 out, fp16
__device__ __align__(16) uint2 g_Bfrag2[NKS2 * 4 * 32];         // conv2 W frags (hi)
__device__ __align__(16) uint2 g_B1frag[2 * 4 * 32];            // conv1 W frags (hi)
__device__ __align__(16) uint2 g_W1frag[NKS1 * 25 * 32];        // fc1 W frags (hi)

// ---------------- kernel 0a: prep conv2 W fragments (row-pair packed) ----------------
__global__ void prep_b_frag(const float* __restrict__ w2)
{
    int idx = blockIdx.x * 256 + threadIdx.x;    // ks*128 + nt*32 + lane
    if (idx >= NKS2 * 128) return;
    int lane = idx & 31, nt = (idx >> 5) & 3, ks = idx >> 7;
    int oc = nt * 8 + (lane >> 2), k0 = (lane & 3) * 2;
    int rA = 2 * ks, rB = rA + 1;

    float v[4] = {0.f, 0.f, 0.f, 0.f};
    if (oc < C2) {
        int icA = rA / 7, dyA = rA % 7;
        const float* wa = w2 + ((oc * C1 + icA) * 7 + dyA) * 7;
        v[0] = wa[k0];
        if (k0 + 1 < 7) v[1] = wa[k0 + 1];
        if (rB <= 104) {
            int icB = rB / 7, dyB = rB % 7;
            const float* wb = w2 + ((oc * C1 + icB) * 7 + dyB) * 7;
            v[2] = wb[k0];
            if (k0 + 1 < 7) v[3] = wb[k0 + 1];
        }
    }
    uint2 q;
    q.x = (u32)f16_bits(v[0]) | ((u32)f16_bits(v[1]) << 16);
    q.y = (u32)f16_bits(v[2]) | ((u32)f16_bits(v[3]) << 16);
    g_Bfrag2[idx] = q;
}

// ---------------- kernel 0b: prep conv1 W fragments ----------------
__global__ void prep_b1_frag(const float* __restrict__ w1)
{
    int idx = threadIdx.x;               // 256 threads
    int lane = idx & 31, ks = (idx >> 5) & 3, nt = idx >> 7;
    int oc = nt * 8 + (lane >> 2), k0 = (lane & 3) * 2;
    int dy0 = ks * 2, dy1 = dy0 + 1;

    float v[4] = {0.f, 0.f, 0.f, 0.f};
    if (oc < C1) {
        const float* wb = w1 + oc * 49;
        v[0] = wb[dy0 * 7 + k0];
        if (k0 + 1 < 7) v[1] = wb[dy0 * 7 + k0 + 1];
        if (dy1 < 7) {
            v[2] = wb[dy1 * 7 + k0];
            if (k0 + 1 < 7) v[3] = wb[dy1 * 7 + k0 + 1];
        }
    }
    uint2 q;
    q.x = (u32)f16_bits(v[0]) | ((u32)f16_bits(v[1]) << 16);
    q.y = (u32)f16_bits(v[2]) | ((u32)f16_bits(v[3]) << 16);
    g_B1frag[(nt * 4 + ks) * 32 + lane] = q;
}

// ---------------- kernel 0c: prep fc1 W fragments ----------------
__global__ void prep_w1_frag(const float* __restrict__ w)
{
    int idx = blockIdx.x * 256 + threadIdx.x;
    if (idx >= NKS1 * 25 * 32) return;
    int lane = idx & 31;
    int nt = (idx >> 5) % 25;
    int ks = idx / (25 * 32);
    int o = nt * 8 + (lane >> 2);
    int k0 = ks * 16 + (lane & 3) * 2;
    const float* wr = w + (size_t)o * FC1_IN;

    float v[4];
    v[0] = (k0     < FC1_IN) ? wr[k0]     : 0.f;
    v[1] = (k0 + 1 < FC1_IN) ? wr[k0 + 1] : 0.f;
    v[2] = (k0 + 8 < FC1_IN) ? wr[k0 + 8] : 0.f;
    v[3] = (k0 + 9 < FC1_IN) ? wr[k0 + 9] : 0.f;
    uint2 q;
    q.x = (u32)f16_bits(v[0]) | ((u32)f16_bits(v[1]) << 16);
    q.y = (u32)f16_bits(v[2]) | ((u32)f16_bits(v[3]) << 16);
    g_W1frag[idx] = q;
}

// ---------------- kernel 1: PCEN + conv1 (fp16 mma) + BN + ReLU + pool ----------------
// smem: fp32 img [64*65] | hi-even [4224 u16] | hi-odd [4224 u16] | BN
#define PL1 2112                 // u32 per parity copy (66 rows, zero tail)
#define SM1_IMG 0
#define SM1_HE  16640            // 2*4224*2 = 16896 bytes
#define SM1_SC  33536
#define SM1_SH  33600
#define SM1_TOT 33664

__global__ __launch_bounds__(256) void conv1_pcen_kernel(
    const float* __restrict__ x,
    const float* __restrict__ log_s, const float* __restrict__ log_alpha,
    const float* __restrict__ log_delta, const float* __restrict__ log_r,
    const float* __restrict__ b1,
    const float* __restrict__ g,  const float* __restrict__ be,
    const float* __restrict__ mu, const float* __restrict__ va)
{
    extern __shared__ __align__(16) char smem[];
    float* img = (float*)(smem + SM1_IMG);
    u16* hE16 = (u16*)(smem + SM1_HE);
    const u32* pH = (const u32*)(smem + SM1_HE);
    float* scS = (float*)(smem + SM1_SC);
    float* shS = (float*)(smem + SM1_SH);

    const int b = blockIdx.x, t = threadIdx.x;
    const int w = t >> 5, lane = t & 31;
    const float* xb = x + (size_t)b * 4096;

    for (int i = t; i < 4096; i += 256)
        img[(i >> 6) * 65 + (i & 63)] = xb[i];
    if (t < 16) {
        if (t < C1) {
            float inv = g[t] * rsqrtf(va[t] + 1e-5f);
            scS[t] = inv;
            shS[t] = (b1[t] - mu[t]) * inv + be[t];
        } else { scS[t] = 0.f; shS[t] = 0.f; }
    }
    uint2 qf[2][4];
    #pragma unroll
    for (int nt = 0; nt < 2; nt++)
        #pragma unroll
        for (int ks = 0; ks < 4; ks++)
            qf[nt][ks] = g_B1frag[(nt * 4 + ks) * 32 + lane];
    __syncthreads();

    // PCEN recurrence
    if (t < 64) {
        const float s     = expf(log_s[0]);
        const float alpha = expf(log_alpha[0]);
        const float delta = expf(log_delta[0]);
        const float r     = expf(log_r[0]);
        const float oms   = 1.0f - s;
        const float dr    = powf(delta, r);
        float* row = img + t * 65;
        float m = 0.0f;
        #pragma unroll 4
        for (int ww = 0; ww < 64; ww++) {
            float xv = row[ww];
            m = (ww == 0) ? s * xv : oms * m + s * xv;
            float Ma = __powf(m + 1e-6f, alpha);
            row[ww] = __powf(__fdividef(xv, Ma) + delta, r) - dr;
        }
    }
    __syncthreads();

    // hi plane build, even + odd parity copies, zero tail rows 64..65
    {
        u16* hO16 = hE16 + 4224;
        for (int i = t; i < 4224; i += 256) {
            u16 h = 0;
            if (i < 4096) h = f16_bits(img[(i >> 6) * 65 + (i & 63)]);
            hE16[i] = h;
            if (i > 0) hO16[i - 1] = h;
        }
        if (t == 0) hO16[4223] = 0;
    }
    __syncthreads();

    const int r = lane >> 2;
    const int koff = (lane & 3) * 2;

    for (int mt = w; mt < 232; mt += 8) {
        const int py = mt >> 3, xo = mt & 7;
        const int y0 = 2 * py, x0 = xo * 8;
        const int eA = y0 * 64 + x0 + r + koff;
        int i0 = (eA & 1) * PL1 + (eA >> 1);

        float acc[2][4];
        #pragma unroll
        for (int nt = 0; nt < 2; nt++)
            { acc[nt][0]=0.f; acc[nt][1]=0.f; acc[nt][2]=0.f; acc[nt][3]=0.f; }

        u32 hA = pH[i0];
        #pragma unroll
        for (int ks = 0; ks < 4; ks++) {
            u32 hB = pH[i0 + 32];
            u32 hC = pH[i0 + 64];
            #pragma unroll
            for (int nt = 0; nt < 2; nt++) {
                uint2 q = qf[nt][ks];
                mma_f16(acc[nt], hA, hB, hB, hC, q.x, q.y);
            }
            hA = hC;
            i0 += 64;
        }

        #pragma unroll
        for (int nt = 0; nt < 2; nt++) {
            int oc = nt * 8 + (lane & 3) * 2;
            float s0 = scS[oc], h0 = shS[oc];
            float s1 = scS[oc + 1], h1 = shS[oc + 1];
            float m0 = fmaxf(fmaxf(acc[nt][0] * s0 + h0, 0.f),
                             fmaxf(acc[nt][2] * s0 + h0, 0.f));
            float m1 = fmaxf(fmaxf(acc[nt][1] * s1 + h1, 0.f),
                             fmaxf(acc[nt][3] * s1 + h1, 0.f));
            m0 = fmaxf(m0, __shfl_xor_sync(0xFFFFFFFFu, m0, 4));
            m1 = fmaxf(m1, __shfl_xor_sync(0xFFFFFFFFu, m1, 4));
            if (!(r & 1)) {
                int px = (x0 + r) >> 1;
                if (px < P1) {
                    u16* ob = g_p1h + (size_t)b * (C1 * P1 * IN2P) + py * IN2P + px;
                    if (oc < C1)     ob[oc * (P1 * IN2P)] = f16_bits(m0);
                    if (oc + 1 < C1) ob[(oc + 1) * (P1 * IN2P)] = f16_bits(m1);
                }
            }
        }
    }
}

// ---------------- kernel 2: conv2 via fp16 mma (1-term, row-pair K) ----------------
#define PL_U32 6960
#define SM_SC  63888            // stage [484][33] f32 overlays planes
#define SM_SH  64016
#define SM_RT  64144            // rowTab[106]
#define SM_TOT2 64576

__global__ __launch_bounds__(256, 2) void conv2_mma_kernel(
    const float* __restrict__ b2,
    const float* __restrict__ g,  const float* __restrict__ be,
    const float* __restrict__ mu, const float* __restrict__ va)
{
    extern __shared__ __align__(16) char smem[];
    u16* hE16 = (u16*)smem;
    const u32* pH = (const u32*)smem;
    float* scS = (float*)(smem + SM_SC);
    float* shS = (float*)(smem + SM_SH);
    int* rowTab = (int*)(smem + SM_RT);

    const int t = threadIdx.x, w = t >> 5, lane = t & 31;
    const int b = blockIdx.x;

    {
        const u16* src = g_p1h + (size_t)b * 13920;
        u16* hO16 = hE16 + 13920;
        for (int i = t; i < 13920; i += 256) {
            u16 h = src[i];
            hE16[i] = h;
            if (i > 0) hO16[i - 1] = h;
        }
        if (t == 0) hO16[13919] = 0;
    }
    if (t < C2) {
        float inv = g[t] * rsqrtf(va[t] + 1e-5f);
        scS[t] = inv;
        shS[t] = (b2[t] - mu[t]) * inv + be[t];
    }
    if (t < 106) {
        int r = (t < 105) ? t : 104;
        rowTab[t] = ((r / 7) * 29 + (r % 7)) * 16;
    }
    __syncthreads();

    int c0[4], c1[4];
    #pragma unroll
    for (int i = 0; i < 4; i++) {
        int mt = w * 4 + i; if (mt > 30) mt = 30;
        int p0 = mt * 16 + (lane >> 2); if (p0 > 483) p0 = 483;
        int p1 = p0 + 8;                if (p1 > 483) p1 = 483;
        int y0 = p0 / 22, x0 = p0 - y0 * 22;
        int y1 = p1 / 22, x1 = p1 - y1 * 22;
        int dx0 = (lane & 3) * 2;
        c0[i] = (x0 & 1) * PL_U32 + y0 * 16 + ((x0 + dx0 - (x0 & 1)) >> 1);
        c1[i] = (x1 & 1) * PL_U32 + y1 * 16 + ((x1 + dx0 - (x1 & 1)) >> 1);
    }

    float acc[4][4][4];
    #pragma unroll
    for (int i = 0; i < 4; i++)
        #pragma unroll
        for (int n = 0; n < 4; n++)
            { acc[i][n][0]=0.f; acc[i][n][1]=0.f; acc[i][n][2]=0.f; acc[i][n][3]=0.f; }

    #pragma unroll 2
    for (int j = 0; j < NKS2; j++) {
        const int kb0 = rowTab[2 * j];
        const int kb1 = rowTab[2 * j + 1];
        uint2 q0 = g_Bfrag2[(j * 4 + 0) * 32 + lane];
        uint2 q1 = g_Bfrag2[(j * 4 + 1) * 32 + lane];
        uint2 q2 = g_Bfrag2[(j * 4 + 2) * 32 + lane];
        uint2 q3 = g_Bfrag2[(j * 4 + 3) * 32 + lane];
        #pragma unroll
        for (int i = 0; i < 4; i++) {
            u32 ah0 = pH[c0[i] + kb0], ah1 = pH[c1[i] + kb0];
            u32 ah2 = pH[c0[i] + kb1], ah3 = pH[c1[i] + kb1];
            mma_f16(acc[i][0], ah0, ah1, ah2, ah3, q0.x, q0.y);
            mma_f16(acc[i][1], ah0, ah1, ah2, ah3, q1.x, q1.y);
            mma_f16(acc[i][2], ah0, ah1, ah2, ah3, q2.x, q2.y);
            mma_f16(acc[i][3], ah0, ah1, ah2, ah3, q3.x, q3.y);
        }
    }

    __syncthreads();                       // planes dead; reuse as stage
    float* stg = (float*)smem;             // [484][33]
    #pragma unroll
    for (int i = 0; i < 4; i++) {
        int mt = w * 4 + i; if (mt > 30) mt = 30;
        int r0 = mt * 16 + (lane >> 2), r1 = r0 + 8;
        #pragma unroll
        for (int n = 0; n < 4; n++) {
            int oc = n * 8 + (lane & 3) * 2;
            if (oc < C2) {
                float s0 = scS[oc], h0 = shS[oc];
                float s1 = scS[oc + 1], h1 = shS[oc + 1];
                if (r0 < 484) {
                    stg[r0 * 33 + oc]     = fmaxf(acc[i][n][0] * s0 + h0, 0.f);
                    stg[r0 * 33 + oc + 1] = fmaxf(acc[i][n][1] * s1 + h1, 0.f);
                }
                if (r1 < 484) {
                    stg[r1 * 33 + oc]     = fmaxf(acc[i][n][2] * s0 + h0, 0.f);
                    stg[r1 * 33 + oc + 1] = fmaxf(acc[i][n][3] * s1 + h1, 0.f);
                }
            }
        }
    }
    __syncthreads();
    for (int i = t; i < 3630; i += 256) {
        int oc = i / 121, pos = i % 121;
        int py = pos / 11, px = pos % 11;
        int p00 = (2 * py) * 22 + 2 * px;
        float v = fmaxf(fmaxf(stg[p00 * 33 + oc], stg[(p00 + 1) * 33 + oc]),
                        fmaxf(stg[(p00 + 22) * 33 + oc], stg[(p00 + 23) * 33 + oc]));
        g_p2h[(size_t)b * FC1_IN + i] = f16_bits(v);
    }
}

// ---------------- kernel 3: FC1 via fp16 mma (1-term, K-split 8) ----------------
__global__ __launch_bounds__(256, 1) void fc1_mma_kernel()
{
    const int t = threadIdx.x, w = t >> 5, lane = t & 31;
    const int mt = blockIdx.x;
    const int kz = blockIdx.y;

    const int row0 = mt * 128 + w * 16 + (lane >> 2);
    const size_t base0 = (size_t)row0 * FC1_IN;
    const size_t base1 = (size_t)(row0 + 8) * FC1_IN;
    const int koff = (lane & 3) * 2;

    const int ks0 = kz * 28 + (kz < 3 ? kz : 3);
    const int nks = 28 + (kz < 3 ? 1 : 0);

    float acc[25][4];
    #pragma unroll
    for (int n = 0; n < 25; n++)
        { acc[n][0]=0.f; acc[n][1]=0.f; acc[n][2]=0.f; acc[n][3]=0.f; }

    #pragma unroll 1
    for (int ks = ks0; ks < ks0 + nks; ks++) {
        const int k0 = ks * 16 + koff;
        u32 ah0 = *(const u32*)&g_p2h[base0 + k0];
        u32 ah1 = *(const u32*)&g_p2h[base1 + k0];
        u32 ah2 = *(const u32*)&g_p2h[base0 + k0 + 8];
        u32 ah3 = *(const u32*)&g_p2h[base1 + k0 + 8];
        const uint2* bp = &g_W1frag[(size_t)ks * 25 * 32 + lane];
        #pragma unroll
        for (int n = 0; n < 25; n++) {
            uint2 q = bp[n * 32];
            mma_f16(acc[n], ah0, ah1, ah2, ah3, q.x, q.y);
        }
    }

    float* dst = g_fc1p + (size_t)kz * B * FC1_OUT;
    const int r0 = row0, r1 = row0 + 8;
    #pragma unroll
    for (int n = 0; n < 25; n++) {
        int o = n * 8 + (lane & 3) * 2;
        dst[(size_t)r0 * FC1_OUT + o]     = acc[n][0];
        dst[(size_t)r0 * FC1_OUT + o + 1] = acc[n][1];
        dst[(size_t)r1 * FC1_OUT + o]     = acc[n][2];
        dst[(size_t)r1 * FC1_OUT + o + 1] = acc[n][3];
    }
}

// ---------------- kernel 4: FC2 + sigmoid ----------------
__global__ __launch_bounds__(256) void fc2_kernel(
    const float* __restrict__ fc1b,
    const float* __restrict__ w2, const float* __restrict__ b2,
    float* __restrict__ out)
{
    const int warp = threadIdx.x >> 5, lane = threadIdx.x & 31;
    const int b = blockIdx.x * 8 + warp;
    const size_t PS = (size_t)B * FC1_OUT;
    const float* base = g_fc1p + (size_t)b * FC1_OUT;
    float s0 = 0.f, s1 = 0.f;
    for (int o = lane; o < FC1_OUT; o += 32) {
        float v = fc1b[o];
        #pragma unroll
        for (int p = 0; p < KSPLIT; p++)
            v += base[p * PS + o];
        v = fmaxf(v, 0.f);
        s0 += v * w2[o];
        s1 += v * w2[FC1_OUT + o];
    }
    #pragma unroll
    for (int d = 16; d > 0; d >>= 1) {
        s0 += __shfl_xor_sync(0xFFFFFFFFu, s0, d);
        s1 += __shfl_xor_sync(0xFFFFFFFFu, s1, d);
    }
    if (lane == 0) {
        out[2 * b + 0] = 1.f / (1.f + expf(-(s0 + b2[0])));
        out[2 * b + 1] = 1.f / (1.f + expf(-(s1 + b2[1])));
    }
}

// ---------------- launch ----------------
extern "C" void kernel_launch(void* const* d_in, const int* in_sizes, int n_in,
                              void* d_out, int out_size)
{
    const float* x       = (const float*)d_in[0];
    const float* log_s   = (const float*)d_in[1];
    const float* log_a   = (const float*)d_in[2];
    const float* log_d   = (const float*)d_in[3];
    const float* log_r   = (const float*)d_in[4];
    const float* conv1_w = (const float*)d_in[5];
    const float* conv1_b = (const float*)d_in[6];
    const float* bn1_g   = (const float*)d_in[7];
    const float* bn1_b   = (const float*)d_in[8];
    const float* bn1_m   = (const float*)d_in[9];
    const float* bn1_v   = (const float*)d_in[10];
    const float* conv2_w = (const float*)d_in[11];
    const float* conv2_b = (const float*)d_in[12];
    const float* bn2_g   = (const float*)d_in[13];
    const float* bn2_b   = (const float*)d_in[14];
    const float* bn2_m   = (const float*)d_in[15];
    const float* bn2_v   = (const float*)d_in[16];
    const float* fc1_w   = (const float*)d_in[17];
    const float* fc1_b   = (const float*)d_in[18];
    const float* fc2_w   = (const float*)d_in[19];
    const float* fc2_b   = (const float*)d_in[20];
    float* out = (float*)d_out;

    static int smem_set = 0;
    if (!smem_set) {
        cudaFuncSetAttribute(conv2_mma_kernel,
                             cudaFuncAttributeMaxDynamicSharedMemorySize, SM_TOT2);
        cudaFuncSetAttribute(conv1_pcen_kernel,
                             cudaFuncAttributeMaxDynamicSharedMemorySize, SM1_TOT);
        smem_set = 1;
    }

    prep_b_frag<<<(NKS2 * 128 + 255) / 256, 256>>>(conv2_w);
    prep_b1_frag<<<1, 256>>>(conv1_w);
    prep_w1_frag<<<(NKS1 * 25 * 32 + 255) / 256, 256>>>(fc1_w);
    conv1_pcen_kernel<<<B, 256, SM1_TOT>>>(x, log_s, log_a, log_d, log_r,
                                           conv1_b, bn1_g, bn1_b, bn1_m, bn1_v);
    conv2_mma_kernel<<<B, 256, SM_TOT2>>>(conv2_b, bn2_g, bn2_b, bn2_m, bn2_v);
    fc1_mma_kernel<<<dim3(16, KSPLIT), 256>>>();
    fc2_kernel<<<B / 8, 256>>>(fc1_b, fc2_w, fc2_b, out);
}

// round 13
// speedup vs baseline: 1.9126x; 1.0014x over previous
#include <cuda_runtime.h>
#include <cuda_fp16.h>
#include <math.h>
#include <stdint.h>

#define B 2048
#define C1 15
#define C2 30
#define P1 29
#define P2 11
#define IN2P 32
#define FC1_IN (30*11*11)
#define FC1_OUT 200
#define KSPLIT 8
#define NKS1 227              // ceil(3630/16)
#define NKS2 53               // ceil(105/2) conv2 row-pair k-steps

typedef uint16_t u16;
typedef uint32_t u32;

// ---------------- warp mma m16n8k16 fp16 -> f32 ----------------
__device__ __forceinline__ void mma_f16(float* d, u32 a0, u32 a1, u32 a2, u32 a3,
                                        u32 b0, u32 b1) {
    asm volatile(
        "mma.sync.aligned.m16n8k16.row.col.f32.f16.f16.f32 "
        "{%0,%1,%2,%3}, {%4,%5,%6,%7}, {%8,%9}, {%0,%1,%2,%3};"
        : "+f"(d[0]), "+f"(d[1]), "+f"(d[2]), "+f"(d[3])
        : "r"(a0), "r"(a1), "r"(a2), "r"(a3), "r"(b0), "r"(b1));
}

__device__ __forceinline__ u16 f16_bits(float v) {
    return __half_as_ushort(__float2half(v));
}

// ---------------- scratch ----------------
__device__ float g_fc1p[KSPLIT * B * FC1_OUT];
__device__ __align__(4)  u16  g_p1h[B * C1 * P1 * IN2P];        // conv1 out, fp16
__device__ __align__(4)  u16  g_p2h[B * FC1_IN + 64];           // conv2 out, fp16
__device__ __align__(16) uint2 g_Bfrag2[NKS2 * 4 * 32];         // conv2 W frags (hi)
__device__ __align__(16) uint2 g_B1frag[2 * 4 * 32];            // conv1 W frags (hi)
__device__ __align__(16) uint2 g_W1frag[NKS1 * 25 * 32];        // fc1 W frags (hi)

// ---------------- kernel 0a: prep conv2 W fragments (row-pair packed) ----------------
__global__ void prep_b_frag(const float* __restrict__ w2)
{
    int idx = blockIdx.x * 256 + threadIdx.x;    // ks*128 + nt*32 + lane
    if (idx >= NKS2 * 128) return;
    int lane = idx & 31, nt = (idx >> 5) & 3, ks = idx >> 7;
    int oc = nt * 8 + (lane >> 2), k0 = (lane & 3) * 2;
    int rA = 2 * ks, rB = rA + 1;

    float v[4] = {0.f, 0.f, 0.f, 0.f};
    if (oc < C2) {
        int icA = rA / 7, dyA = rA % 7;
        const float* wa = w2 + ((oc * C1 + icA) * 7 + dyA) * 7;
        v[0] = wa[k0];
        if (k0 + 1 < 7) v[1] = wa[k0 + 1];
        if (rB <= 104) {
            int icB = rB / 7, dyB = rB % 7;
            const float* wb = w2 + ((oc * C1 + icB) * 7 + dyB) * 7;
            v[2] = wb[k0];
            if (k0 + 1 < 7) v[3] = wb[k0 + 1];
        }
    }
    uint2 q;
    q.x = (u32)f16_bits(v[0]) | ((u32)f16_bits(v[1]) << 16);
    q.y = (u32)f16_bits(v[2]) | ((u32)f16_bits(v[3]) << 16);
    g_Bfrag2[idx] = q;
}

// ---------------- kernel 0b: prep conv1 W fragments ----------------
__global__ void prep_b1_frag(const float* __restrict__ w1)
{
    int idx = threadIdx.x;               // 256 threads
    int lane = idx & 31, ks = (idx >> 5) & 3, nt = idx >> 7;
    int oc = nt * 8 + (lane >> 2), k0 = (lane & 3) * 2;
    int dy0 = ks * 2, dy1 = dy0 + 1;

    float v[4] = {0.f, 0.f, 0.f, 0.f};
    if (oc < C1) {
        const float* wb = w1 + oc * 49;
        v[0] = wb[dy0 * 7 + k0];
        if (k0 + 1 < 7) v[1] = wb[dy0 * 7 + k0 + 1];
        if (dy1 < 7) {
            v[2] = wb[dy1 * 7 + k0];
            if (k0 + 1 < 7) v[3] = wb[dy1 * 7 + k0 + 1];
        }
    }
    uint2 q;
    q.x = (u32)f16_bits(v[0]) | ((u32)f16_bits(v[1]) << 16);
    q.y = (u32)f16_bits(v[2]) | ((u32)f16_bits(v[3]) << 16);
    g_B1frag[(nt * 4 + ks) * 32 + lane] = q;
}

// ---------------- kernel 0c: prep fc1 W fragments ----------------
__global__ void prep_w1_frag(const float* __restrict__ w)
{
    int idx = blockIdx.x * 256 + threadIdx.x;
    if (idx >= NKS1 * 25 * 32) return;
    int lane = idx & 31;
    int nt = (idx >> 5) % 25;
    int ks = idx / (25 * 32);
    int o = nt * 8 + (lane >> 2);
    int k0 = ks * 16 + (lane & 3) * 2;
    const float* wr = w + (size_t)o * FC1_IN;

    float v[4];
    v[0] = (k0     < FC1_IN) ? wr[k0]     : 0.f;
    v[1] = (k0 + 1 < FC1_IN) ? wr[k0 + 1] : 0.f;
    v[2] = (k0 + 8 < FC1_IN) ? wr[k0 + 8] : 0.f;
    v[3] = (k0 + 9 < FC1_IN) ? wr[k0 + 9] : 0.f;
    uint2 q;
    q.x = (u32)f16_bits(v[0]) | ((u32)f16_bits(v[1]) << 16);
    q.y = (u32)f16_bits(v[2]) | ((u32)f16_bits(v[3]) << 16);
    g_W1frag[idx] = q;
}

// ---------------- kernel 1: PCEN + conv1 (fp16 mma) + BN + ReLU + pool ----------------
// smem: fp32 img [64*65] | hi-even [4224 u16] | hi-odd [4224 u16] | BN
#define PL1 2112                 // u32 per parity copy (66 rows, zero tail)
#define SM1_IMG 0
#define SM1_HE  16640            // 2*4224*2 = 16896 bytes
#define SM1_SC  33536
#define SM1_SH  33600
#define SM1_TOT 33664

__global__ __launch_bounds__(256) void conv1_pcen_kernel(
    const float* __restrict__ x,
    const float* __restrict__ log_s, const float* __restrict__ log_alpha,
    const float* __restrict__ log_delta, const float* __restrict__ log_r,
    const float* __restrict__ b1,
    const float* __restrict__ g,  const float* __restrict__ be,
    const float* __restrict__ mu, const float* __restrict__ va)
{
    extern __shared__ __align__(16) char smem[];
    float* img = (float*)(smem + SM1_IMG);
    u16* hE16 = (u16*)(smem + SM1_HE);
    const u32* pH = (const u32*)(smem + SM1_HE);
    float* scS = (float*)(smem + SM1_SC);
    float* shS = (float*)(smem + SM1_SH);

    const int b = blockIdx.x, t = threadIdx.x;
    const int w = t >> 5, lane = t & 31;
    const float* xb = x + (size_t)b * 4096;

    for (int i = t; i < 4096; i += 256)
        img[(i >> 6) * 65 + (i & 63)] = xb[i];
    if (t < 16) {
        if (t < C1) {
            float inv = g[t] * rsqrtf(va[t] + 1e-5f);
            scS[t] = inv;
            shS[t] = (b1[t] - mu[t]) * inv + be[t];
        } else { scS[t] = 0.f; shS[t] = 0.f; }
    }
    uint2 qf[2][4];
    #pragma unroll
    for (int nt = 0; nt < 2; nt++)
        #pragma unroll
        for (int ks = 0; ks < 4; ks++)
            qf[nt][ks] = g_B1frag[(nt * 4 + ks) * 32 + lane];
    __syncthreads();

    // PCEN recurrence
    if (t < 64) {
        const float s     = expf(log_s[0]);
        const float alpha = expf(log_alpha[0]);
        const float delta = expf(log_delta[0]);
        const float r     = expf(log_r[0]);
        const float oms   = 1.0f - s;
        const float dr    = powf(delta, r);
        float* row = img + t * 65;
        float m = 0.0f;
        #pragma unroll 4
        for (int ww = 0; ww < 64; ww++) {
            float xv = row[ww];
            m = (ww == 0) ? s * xv : oms * m + s * xv;
            float Ma = __powf(m + 1e-6f, alpha);
            row[ww] = __powf(__fdividef(xv, Ma) + delta, r) - dr;
        }
    }
    __syncthreads();

    // hi plane build, even + odd parity copies, zero tail rows 64..65
    {
        u16* hO16 = hE16 + 4224;
        for (int i = t; i < 4224; i += 256) {
            u16 h = 0;
            if (i < 4096) h = f16_bits(img[(i >> 6) * 65 + (i & 63)]);
            hE16[i] = h;
            if (i > 0) hO16[i - 1] = h;
        }
        if (t == 0) hO16[4223] = 0;
    }
    __syncthreads();

    const int r = lane >> 2;
    const int koff = (lane & 3) * 2;

    for (int mt = w; mt < 232; mt += 8) {
        const int py = mt >> 3, xo = mt & 7;
        const int y0 = 2 * py, x0 = xo * 8;
        const int eA = y0 * 64 + x0 + r + koff;
        int i0 = (eA & 1) * PL1 + (eA >> 1);

        float acc[2][4];
        #pragma unroll
        for (int nt = 0; nt < 2; nt++)
            { acc[nt][0]=0.f; acc[nt][1]=0.f; acc[nt][2]=0.f; acc[nt][3]=0.f; }

        u32 hA = pH[i0];
        #pragma unroll
        for (int ks = 0; ks < 4; ks++) {
            u32 hB = pH[i0 + 32];
            u32 hC = pH[i0 + 64];
            #pragma unroll
            for (int nt = 0; nt < 2; nt++) {
                uint2 q = qf[nt][ks];
                mma_f16(acc[nt], hA, hB, hB, hC, q.x, q.y);
            }
            hA = hC;
            i0 += 64;
        }

        #pragma unroll
        for (int nt = 0; nt < 2; nt++) {
            int oc = nt * 8 + (lane & 3) * 2;
            float s0 = scS[oc], h0 = shS[oc];
            float s1 = scS[oc + 1], h1 = shS[oc + 1];
            float m0 = fmaxf(fmaxf(acc[nt][0] * s0 + h0, 0.f),
                             fmaxf(acc[nt][2] * s0 + h0, 0.f));
            float m1 = fmaxf(fmaxf(acc[nt][1] * s1 + h1, 0.f),
                             fmaxf(acc[nt][3] * s1 + h1, 0.f));
            m0 = fmaxf(m0, __shfl_xor_sync(0xFFFFFFFFu, m0, 4));
            m1 = fmaxf(m1, __shfl_xor_sync(0xFFFFFFFFu, m1, 4));
            if (!(r & 1)) {
                int px = (x0 + r) >> 1;
                if (px < P1) {
                    u16* ob = g_p1h + (size_t)b * (C1 * P1 * IN2P) + py * IN2P + px;
                    if (oc < C1)     ob[oc * (P1 * IN2P)] = f16_bits(m0);
                    if (oc + 1 < C1) ob[(oc + 1) * (P1 * IN2P)] = f16_bits(m1);
                }
            }
        }
    }
}

// ---------------- kernel 2: conv2 via fp16 mma (1-term, row-pair K) ----------------
#define PL_U32 6960
#define SM_SC  63888            // stage [484][33] f32 overlays planes
#define SM_SH  64016
#define SM_RT  64144            // rowTab[106]
#define SM_TOT2 64576

__global__ __launch_bounds__(256, 2) void conv2_mma_kernel(
    const float* __restrict__ b2,
    const float* __restrict__ g,  const float* __restrict__ be,
    const float* __restrict__ mu, const float* __restrict__ va)
{
    extern __shared__ __align__(16) char smem[];
    u16* hE16 = (u16*)smem;
    const u32* pH = (const u32*)smem;
    float* scS = (float*)(smem + SM_SC);
    float* shS = (float*)(smem + SM_SH);
    int* rowTab = (int*)(smem + SM_RT);

    const int t = threadIdx.x, w = t >> 5, lane = t & 31;
    const int b = blockIdx.x;

    {
        const u16* src = g_p1h + (size_t)b * 13920;
        u16* hO16 = hE16 + 13920;
        for (int i = t; i < 13920; i += 256) {
            u16 h = src[i];
            hE16[i] = h;
            if (i > 0) hO16[i - 1] = h;
        }
        if (t == 0) hO16[13919] = 0;
    }
    if (t < C2) {
        float inv = g[t] * rsqrtf(va[t] + 1e-5f);
        scS[t] = inv;
        shS[t] = (b2[t] - mu[t]) * inv + be[t];
    }
    if (t < 106) {
        int r = (t < 105) ? t : 104;
        rowTab[t] = ((r / 7) * 29 + (r % 7)) * 16;
    }
    __syncthreads();

    int c0[4], c1[4];
    #pragma unroll
    for (int i = 0; i < 4; i++) {
        int mt = w * 4 + i; if (mt > 30) mt = 30;
        int p0 = mt * 16 + (lane >> 2); if (p0 > 483) p0 = 483;
        int p1 = p0 + 8;                if (p1 > 483) p1 = 483;
        int y0 = p0 / 22, x0 = p0 - y0 * 22;
        int y1 = p1 / 22, x1 = p1 - y1 * 22;
        int dx0 = (lane & 3) * 2;
        c0[i] = (x0 & 1) * PL_U32 + y0 * 16 + ((x0 + dx0 - (x0 & 1)) >> 1);
        c1[i] = (x1 & 1) * PL_U32 + y1 * 16 + ((x1 + dx0 - (x1 & 1)) >> 1);
    }

    float acc[4][4][4];
    #pragma unroll
    for (int i = 0; i < 4; i++)
        #pragma unroll
        for (int n = 0; n < 4; n++)
            { acc[i][n][0]=0.f; acc[i][n][1]=0.f; acc[i][n][2]=0.f; acc[i][n][3]=0.f; }

    #pragma unroll 2
    for (int j = 0; j < NKS2; j++) {
        const int kb0 = rowTab[2 * j];
        const int kb1 = rowTab[2 * j + 1];
        uint2 q0 = g_Bfrag2[(j * 4 + 0) * 32 + lane];
        uint2 q1 = g_Bfrag2[(j * 4 + 1) * 32 + lane];
        uint2 q2 = g_Bfrag2[(j * 4 + 2) * 32 + lane];
        uint2 q3 = g_Bfrag2[(j * 4 + 3) * 32 + lane];
        #pragma unroll
        for (int i = 0; i < 4; i++) {
            u32 ah0 = pH[c0[i] + kb0], ah1 = pH[c1[i] + kb0];
            u32 ah2 = pH[c0[i] + kb1], ah3 = pH[c1[i] + kb1];
            mma_f16(acc[i][0], ah0, ah1, ah2, ah3, q0.x, q0.y);
            mma_f16(acc[i][1], ah0, ah1, ah2, ah3, q1.x, q1.y);
            mma_f16(acc[i][2], ah0, ah1, ah2, ah3, q2.x, q2.y);
            mma_f16(acc[i][3], ah0, ah1, ah2, ah3, q3.x, q3.y);
        }
    }

    __syncthreads();                       // planes dead; reuse as stage
    float* stg = (float*)smem;             // [484][33]
    #pragma unroll
    for (int i = 0; i < 4; i++) {
        int mt = w * 4 + i; if (mt > 30) mt = 30;
        int r0 = mt * 16 + (lane >> 2), r1 = r0 + 8;
        #pragma unroll
        for (int n = 0; n < 4; n++) {
            int oc = n * 8 + (lane & 3) * 2;
            if (oc < C2) {
                float s0 = scS[oc], h0 = shS[oc];
                float s1 = scS[oc + 1], h1 = shS[oc + 1];
                if (r0 < 484) {
                    stg[r0 * 33 + oc]     = fmaxf(acc[i][n][0] * s0 + h0, 0.f);
                    stg[r0 * 33 + oc + 1] = fmaxf(acc[i][n][1] * s1 + h1, 0.f);
                }
                if (r1 < 484) {
                    stg[r1 * 33 + oc]     = fmaxf(acc[i][n][2] * s0 + h0, 0.f);
                    stg[r1 * 33 + oc + 1] = fmaxf(acc[i][n][3] * s1 + h1, 0.f);
                }
            }
        }
    }
    __syncthreads();
    for (int i = t; i < 3630; i += 256) {
        int oc = i / 121, pos = i % 121;
        int py = pos / 11, px = pos % 11;
        int p00 = (2 * py) * 22 + 2 * px;
        float v = fmaxf(fmaxf(stg[p00 * 33 + oc], stg[(p00 + 1) * 33 + oc]),
                        fmaxf(stg[(p00 + 22) * 33 + oc], stg[(p00 + 23) * 33 + oc]));
        g_p2h[(size_t)b * FC1_IN + i] = f16_bits(v);
    }
}

// ---------------- kernel 3: FC1 via fp16 mma (1-term, K-split 8) ----------------
__global__ __launch_bounds__(256, 1) void fc1_mma_kernel()
{
    const int t = threadIdx.x, w = t >> 5, lane = t & 31;
    const int mt = blockIdx.x;
    const int kz = blockIdx.y;

    const int row0 = mt * 128 + w * 16 + (lane >> 2);
    const size_t base0 = (size_t)row0 * FC1_IN;
    const size_t base1 = (size_t)(row0 + 8) * FC1_IN;
    const int koff = (lane & 3) * 2;

    const int ks0 = kz * 28 + (kz < 3 ? kz : 3);
    const int nks = 28 + (kz < 3 ? 1 : 0);

    float acc[25][4];
    #pragma unroll
    for (int n = 0; n < 25; n++)
        { acc[n][0]=0.f; acc[n][1]=0.f; acc[n][2]=0.f; acc[n][3]=0.f; }

    #pragma unroll 1
    for (int ks = ks0; ks < ks0 + nks; ks++) {
        const int k0 = ks * 16 + koff;
        u32 ah0 = *(const u32*)&g_p2h[base0 + k0];
        u32 ah1 = *(const u32*)&g_p2h[base1 + k0];
        u32 ah2 = *(const u32*)&g_p2h[base0 + k0 + 8];
        u32 ah3 = *(const u32*)&g_p2h[base1 + k0 + 8];
        const uint2* bp = &g_W1frag[(size_t)ks * 25 * 32 + lane];
        #pragma unroll
        for (int n = 0; n < 25; n++) {
            uint2 q = bp[n * 32];
            mma_f16(acc[n], ah0, ah1, ah2, ah3, q.x, q.y);
        }
    }

    float* dst = g_fc1p + (size_t)kz * B * FC1_OUT;
    const int r0 = row0, r1 = row0 + 8;
    #pragma unroll
    for (int n = 0; n < 25; n++) {
        int o = n * 8 + (lane & 3) * 2;
        dst[(size_t)r0 * FC1_OUT + o]     = acc[n][0];
        dst[(size_t)r0 * FC1_OUT + o + 1] = acc[n][1];
        dst[(size_t)r1 * FC1_OUT + o]     = acc[n][2];
        dst[(size_t)r1 * FC1_OUT + o + 1] = acc[n][3];
    }
}

// ---------------- kernel 4: FC2 + sigmoid ----------------
__global__ __launch_bounds__(256) void fc2_kernel(
    const float* __restrict__ fc1b,
    const float* __restrict__ w2, const float* __restrict__ b2,
    float* __restrict__ out)
{
    const int warp = threadIdx.x >> 5, lane = threadIdx.x & 31;
    const int b = blockIdx.x * 8 + warp;
    const size_t PS = (size_t)B * FC1_OUT;
    const float* base = g_fc1p + (size_t)b * FC1_OUT;
    float s0 = 0.f, s1 = 0.f;
    for (int o = lane; o < FC1_OUT; o += 32) {
        float v = fc1b[o];
        #pragma unroll
        for (int p = 0; p < KSPLIT; p++)
            v += base[p * PS + o];
        v = fmaxf(v, 0.f);
        s0 += v * w2[o];
        s1 += v * w2[FC1_OUT + o];
    }
    #pragma unroll
    for (int d = 16; d > 0; d >>= 1) {
        s0 += __shfl_xor_sync(0xFFFFFFFFu, s0, d);
        s1 += __shfl_xor_sync(0xFFFFFFFFu, s1, d);
    }
    if (lane == 0) {
        out[2 * b + 0] = 1.f / (1.f + expf(-(s0 + b2[0])));
        out[2 * b + 1] = 1.f / (1.f + expf(-(s1 + b2[1])));
    }
}

// ---------------- launch ----------------
extern "C" void kernel_launch(void* const* d_in, const int* in_sizes, int n_in,
                              void* d_out, int out_size)
{
    const float* x       = (const float*)d_in[0];
    const float* log_s   = (const float*)d_in[1];
    const float* log_a   = (const float*)d_in[2];
    const float* log_d   = (const float*)d_in[3];
    const float* log_r   = (const float*)d_in[4];
    const float* conv1_w = (const float*)d_in[5];
    const float* conv1_b = (const float*)d_in[6];
    const float* bn1_g   = (const float*)d_in[7];
    const float* bn1_b   = (const float*)d_in[8];
    const float* bn1_m   = (const float*)d_in[9];
    const float* bn1_v   = (const float*)d_in[10];
    const float* conv2_w = (const float*)d_in[11];
    const float* conv2_b = (const float*)d_in[12];
    const float* bn2_g   = (const float*)d_in[13];
    const float* bn2_b   = (const float*)d_in[14];
    const float* bn2_m   = (const float*)d_in[15];
    const float* bn2_v   = (const float*)d_in[16];
    const float* fc1_w   = (const float*)d_in[17];
    const float* fc1_b   = (const float*)d_in[18];
    const float* fc2_w   = (const float*)d_in[19];
    const float* fc2_b   = (const float*)d_in[20];
    float* out = (float*)d_out;

    static int smem_set = 0;
    if (!smem_set) {
        cudaFuncSetAttribute(conv2_mma_kernel,
                             cudaFuncAttributeMaxDynamicSharedMemorySize, SM_TOT2);
        cudaFuncSetAttribute(conv1_pcen_kernel,
                             cudaFuncAttributeMaxDynamicSharedMemorySize, SM1_TOT);
        smem_set = 1;
    }

    prep_b_frag<<<(NKS2 * 128 + 255) / 256, 256>>>(conv2_w);
    prep_b1_frag<<<1, 256>>>(conv1_w);
    prep_w1_frag<<<(NKS1 * 25 * 32 + 255) / 256, 256>>>(fc1_w);
    conv1_pcen_kernel<<<B, 256, SM1_TOT>>>(x, log_s, log_a, log_d, log_r,
                                           conv1_b, bn1_g, bn1_b, bn1_m, bn1_v);
    conv2_mma_kernel<<<B, 256, SM_TOT2>>>(conv2_b, bn2_g, bn2_b, bn2_m, bn2_v);
    fc1_mma_kernel<<<dim3(16, KSPLIT), 256>>>();
    fc2_kernel<<<B / 8, 256>>>(fc1_b, fc2_w, fc2_b, out);
}

// round 14
// speedup vs baseline: 1.9336x; 1.0110x over previous
#include <cuda_runtime.h>
#include <cuda_fp16.h>
#include <math.h>
#include <stdint.h>

#define B 2048
#define C1 15
#define C2 30
#define P1 29
#define P2 11
#define IN2P 32
#define FC1_IN (30*11*11)
#define FC1_OUT 200
#define KSPLIT 8
#define NKS1 227              // ceil(3630/16)
#define NKS2 53               // ceil(105/2) conv2 row-pair k-steps

typedef uint16_t u16;
typedef uint32_t u32;

// ---------------- warp mma m16n8k16 fp16 -> f32 ----------------
__device__ __forceinline__ void mma_f16(float* d, u32 a0, u32 a1, u32 a2, u32 a3,
                                        u32 b0, u32 b1) {
    asm volatile(
        "mma.sync.aligned.m16n8k16.row.col.f32.f16.f16.f32 "
        "{%0,%1,%2,%3}, {%4,%5,%6,%7}, {%8,%9}, {%0,%1,%2,%3};"
        : "+f"(d[0]), "+f"(d[1]), "+f"(d[2]), "+f"(d[3])
        : "r"(a0), "r"(a1), "r"(a2), "r"(a3), "r"(b0), "r"(b1));
}

__device__ __forceinline__ u16 f16_bits(float v) {
    return __half_as_ushort(__float2half(v));
}
__device__ __forceinline__ float f16_val(u16 b) {
    return __half2float(__ushort_as_half(b));
}

// ---------------- scratch ----------------
__device__ float g_fc1p[KSPLIT * B * FC1_OUT];
__device__ __align__(4)  u16  g_p2h[B * FC1_IN + 64];           // conv2 out, fp16
__device__ __align__(16) uint2 g_Bfrag2[NKS2 * 4 * 32];         // conv2 W frags
__device__ __align__(16) uint2 g_B1frag[2 * 4 * 32];            // conv1 W frags
__device__ __align__(16) uint2 g_W1frag[NKS1 * 25 * 32];        // fc1 W frags

// ---------------- kernel 0a: prep conv2 W fragments (row-pair packed) ----------------
__global__ void prep_b_frag(const float* __restrict__ w2)
{
    int idx = blockIdx.x * 256 + threadIdx.x;
    if (idx >= NKS2 * 128) return;
    int lane = idx & 31, nt = (idx >> 5) & 3, ks = idx >> 7;
    int oc = nt * 8 + (lane >> 2), k0 = (lane & 3) * 2;
    int rA = 2 * ks, rB = rA + 1;

    float v[4] = {0.f, 0.f, 0.f, 0.f};
    if (oc < C2) {
        int icA = rA / 7, dyA = rA % 7;
        const float* wa = w2 + ((oc * C1 + icA) * 7 + dyA) * 7;
        v[0] = wa[k0];
        if (k0 + 1 < 7) v[1] = wa[k0 + 1];
        if (rB <= 104) {
            int icB = rB / 7, dyB = rB % 7;
            const float* wb = w2 + ((oc * C1 + icB) * 7 + dyB) * 7;
            v[2] = wb[k0];
            if (k0 + 1 < 7) v[3] = wb[k0 + 1];
        }
    }
    uint2 q;
    q.x = (u32)f16_bits(v[0]) | ((u32)f16_bits(v[1]) << 16);
    q.y = (u32)f16_bits(v[2]) | ((u32)f16_bits(v[3]) << 16);
    g_Bfrag2[idx] = q;
}

// ---------------- kernel 0b: prep conv1 W fragments ----------------
__global__ void prep_b1_frag(const float* __restrict__ w1)
{
    int idx = threadIdx.x;               // 256 threads
    int lane = idx & 31, ks = (idx >> 5) & 3, nt = idx >> 7;
    int oc = nt * 8 + (lane >> 2), k0 = (lane & 3) * 2;
    int dy0 = ks * 2, dy1 = dy0 + 1;

    float v[4] = {0.f, 0.f, 0.f, 0.f};
    if (oc < C1) {
        const float* wb = w1 + oc * 49;
        v[0] = wb[dy0 * 7 + k0];
        if (k0 + 1 < 7) v[1] = wb[dy0 * 7 + k0 + 1];
        if (dy1 < 7) {
            v[2] = wb[dy1 * 7 + k0];
            if (k0 + 1 < 7) v[3] = wb[dy1 * 7 + k0 + 1];
        }
    }
    uint2 q;
    q.x = (u32)f16_bits(v[0]) | ((u32)f16_bits(v[1]) << 16);
    q.y = (u32)f16_bits(v[2]) | ((u32)f16_bits(v[3]) << 16);
    g_B1frag[(nt * 4 + ks) * 32 + lane] = q;
}

// ---------------- kernel 0c: prep fc1 W fragments ----------------
__global__ void prep_w1_frag(const float* __restrict__ w)
{
    int idx = blockIdx.x * 256 + threadIdx.x;
    if (idx >= NKS1 * 25 * 32) return;
    int lane = idx & 31;
    int nt = (idx >> 5) % 25;
    int ks = idx / (25 * 32);
    int o = nt * 8 + (lane >> 2);
    int k0 = ks * 16 + (lane & 3) * 2;
    const float* wr = w + (size_t)o * FC1_IN;

    float v[4];
    v[0] = (k0     < FC1_IN) ? wr[k0]     : 0.f;
    v[1] = (k0 + 1 < FC1_IN) ? wr[k0 + 1] : 0.f;
    v[2] = (k0 + 8 < FC1_IN) ? wr[k0 + 8] : 0.f;
    v[3] = (k0 + 9 < FC1_IN) ? wr[k0 + 9] : 0.f;
    uint2 q;
    q.x = (u32)f16_bits(v[0]) | ((u32)f16_bits(v[1]) << 16);
    q.y = (u32)f16_bits(v[2]) | ((u32)f16_bits(v[3]) << 16);
    g_W1frag[idx] = q;
}

// ---------------- kernel 1: fused PCEN + conv1 + conv2 + pools ----------------
// smem regions (bytes):
//   P    [0, 55680)        conv2 parity planes (u16 x 13920 x 2); later stage u16[484][33]
//   IMG  [55680, 72320)    fp32 image 64x65
//   C1P  [72320, 89216)    conv1 parity planes (u16 x 4224 x 2)
//   consts [89216, 90112)
#define PL1 2112                 // u32 per conv1 parity copy
#define PL2 6960                 // u32 per conv2 parity copy
#define MM_P    0
#define MM_IMG  55680
#define MM_C1P  72320
#define MM_SC1  89216
#define MM_SH1  89280
#define MM_SC2  89344
#define MM_SH2  89472
#define MM_RT   89600
#define MM_TOT  90112

__global__ __launch_bounds__(256, 2) void conv_fused_kernel(
    const float* __restrict__ x,
    const float* __restrict__ log_s, const float* __restrict__ log_alpha,
    const float* __restrict__ log_delta, const float* __restrict__ log_r,
    const float* __restrict__ b1,
    const float* __restrict__ g1,  const float* __restrict__ be1,
    const float* __restrict__ mu1, const float* __restrict__ va1,
    const float* __restrict__ b2,
    const float* __restrict__ g2,  const float* __restrict__ be2,
    const float* __restrict__ mu2, const float* __restrict__ va2)
{
    extern __shared__ __align__(16) char smem[];
    u16* pP16 = (u16*)(smem + MM_P);             // conv2 planes (even @0, odd @13920)
    u32* pP32 = (u32*)(smem + MM_P);
    const u32* pH2 = (const u32*)(smem + MM_P);
    float* img = (float*)(smem + MM_IMG);
    u16* c1E16 = (u16*)(smem + MM_C1P);
    const u32* pH1 = (const u32*)(smem + MM_C1P);
    float* sc1 = (float*)(smem + MM_SC1);
    float* sh1 = (float*)(smem + MM_SH1);
    float* sc2 = (float*)(smem + MM_SC2);
    float* sh2 = (float*)(smem + MM_SH2);
    int* rowTab = (int*)(smem + MM_RT);

    const int b = blockIdx.x, t = threadIdx.x;
    const int w = t >> 5, lane = t & 31;
    const float* xb = x + (size_t)b * 4096;

    // ---- phase 0: loads + consts ----
    for (int i = t; i < 4096; i += 256)
        img[(i >> 6) * 65 + (i & 63)] = xb[i];
    for (int i = t; i < 13920; i += 256)
        pP32[i] = 0u;                       // zero conv2 plane region (padding!)
    if (t < 16) {
        if (t < C1) {
            float inv = g1[t] * rsqrtf(va1[t] + 1e-5f);
            sc1[t] = inv;
            sh1[t] = (b1[t] - mu1[t]) * inv + be1[t];
        } else { sc1[t] = 0.f; sh1[t] = 0.f; }
    }
    if (t >= 32 && t < 32 + C2) {
        int c = t - 32;
        float inv = g2[c] * rsqrtf(va2[c] + 1e-5f);
        sc2[c] = inv;
        sh2[c] = (b2[c] - mu2[c]) * inv + be2[c];
    }
    if (t >= 64 && t < 170) {
        int i = t - 64;
        int r = (i < 105) ? i : 104;
        rowTab[i] = ((r / 7) * 29 + (r % 7)) * 16;
    }
    uint2 qf[2][4];
    #pragma unroll
    for (int nt = 0; nt < 2; nt++)
        #pragma unroll
        for (int ks = 0; ks < 4; ks++)
            qf[nt][ks] = g_B1frag[(nt * 4 + ks) * 32 + lane];
    __syncthreads();

    // ---- phase 1: PCEN recurrence (thread t<64 owns row t) ----
    if (t < 64) {
        const float s     = expf(log_s[0]);
        const float alpha = expf(log_alpha[0]);
        const float delta = expf(log_delta[0]);
        const float r     = expf(log_r[0]);
        const float oms   = 1.0f - s;
        const float dr    = powf(delta, r);
        float* row = img + t * 65;
        float m = 0.0f;
        #pragma unroll 4
        for (int ww = 0; ww < 64; ww++) {
            float xv = row[ww];
            m = (ww == 0) ? s * xv : oms * m + s * xv;
            float Ma = __powf(m + 1e-6f, alpha);
            row[ww] = __powf(__fdividef(xv, Ma) + delta, r) - dr;
        }
    }
    __syncthreads();

    // ---- phase 2: conv1 parity planes (zero tail rows 64..65) ----
    {
        u16* c1O16 = c1E16 + 4224;
        for (int i = t; i < 4224; i += 256) {
            u16 h = 0;
            if (i < 4096) h = f16_bits(img[(i >> 6) * 65 + (i & 63)]);
            c1E16[i] = h;
            if (i > 0) c1O16[i - 1] = h;
        }
        if (t == 0) c1O16[4223] = 0;
    }
    __syncthreads();

    // ---- phase 3: conv1 MMA + BN/ReLU/pool -> conv2 planes (both parities) ----
    {
        const int r = lane >> 2;
        const int koff = (lane & 3) * 2;
        for (int mt = w; mt < 232; mt += 8) {
            const int py = mt >> 3, xo = mt & 7;
            const int y0 = 2 * py, x0 = xo * 8;
            const int eA = y0 * 64 + x0 + r + koff;
            int i0 = (eA & 1) * PL1 + (eA >> 1);

            float acc[2][4];
            #pragma unroll
            for (int nt = 0; nt < 2; nt++)
                { acc[nt][0]=0.f; acc[nt][1]=0.f; acc[nt][2]=0.f; acc[nt][3]=0.f; }

            u32 hA = pH1[i0];
            #pragma unroll
            for (int ks = 0; ks < 4; ks++) {
                u32 hB = pH1[i0 + 32];
                u32 hC = pH1[i0 + 64];
                #pragma unroll
                for (int nt = 0; nt < 2; nt++)
                    mma_f16(acc[nt], hA, hB, hB, hC, qf[nt][ks].x, qf[nt][ks].y);
                hA = hC;
                i0 += 64;
            }

            #pragma unroll
            for (int nt = 0; nt < 2; nt++) {
                int oc = nt * 8 + (lane & 3) * 2;
                float s0 = sc1[oc], h0 = sh1[oc];
                float s1 = sc1[oc + 1], h1 = sh1[oc + 1];
                float m0 = fmaxf(fmaxf(acc[nt][0] * s0 + h0, 0.f),
                                 fmaxf(acc[nt][2] * s0 + h0, 0.f));
                float m1 = fmaxf(fmaxf(acc[nt][1] * s1 + h1, 0.f),
                                 fmaxf(acc[nt][3] * s1 + h1, 0.f));
                m0 = fmaxf(m0, __shfl_xor_sync(0xFFFFFFFFu, m0, 4));
                m1 = fmaxf(m1, __shfl_xor_sync(0xFFFFFFFFu, m1, 4));
                if (!(r & 1)) {
                    int px = (x0 + r) >> 1;
                    if (px < P1) {
                        if (oc < C1) {
                            int e = oc * 928 + py * 32 + px;
                            u16 hv = f16_bits(m0);
                            pP16[e] = hv;
                            if (e > 0) pP16[13920 + e - 1] = hv;
                        }
                        if (oc + 1 < C1) {
                            int e = (oc + 1) * 928 + py * 32 + px;
                            u16 hv = f16_bits(m1);
                            pP16[e] = hv;
                            pP16[13920 + e - 1] = hv;
                        }
                    }
                }
            }
        }
    }
    __syncthreads();

    // ---- phase 4: conv2 MMA ----
    int c0[4], c1[4];
    #pragma unroll
    for (int i = 0; i < 4; i++) {
        int mt = w * 4 + i; if (mt > 30) mt = 30;
        int p0 = mt * 16 + (lane >> 2); if (p0 > 483) p0 = 483;
        int p1 = p0 + 8;                if (p1 > 483) p1 = 483;
        int y0 = p0 / 22, x0 = p0 - y0 * 22;
        int y1 = p1 / 22, x1 = p1 - y1 * 22;
        int dx0 = (lane & 3) * 2;
        c0[i] = (x0 & 1) * PL2 + y0 * 16 + ((x0 + dx0 - (x0 & 1)) >> 1);
        c1[i] = (x1 & 1) * PL2 + y1 * 16 + ((x1 + dx0 - (x1 & 1)) >> 1);
    }

    float acc[4][4][4];
    #pragma unroll
    for (int i = 0; i < 4; i++)
        #pragma unroll
        for (int n = 0; n < 4; n++)
            { acc[i][n][0]=0.f; acc[i][n][1]=0.f; acc[i][n][2]=0.f; acc[i][n][3]=0.f; }

    #pragma unroll 2
    for (int j = 0; j < NKS2; j++) {
        const int kb0 = rowTab[2 * j];
        const int kb1 = rowTab[2 * j + 1];
        uint2 q0 = g_Bfrag2[(j * 4 + 0) * 32 + lane];
        uint2 q1 = g_Bfrag2[(j * 4 + 1) * 32 + lane];
        uint2 q2 = g_Bfrag2[(j * 4 + 2) * 32 + lane];
        uint2 q3 = g_Bfrag2[(j * 4 + 3) * 32 + lane];
        #pragma unroll
        for (int i = 0; i < 4; i++) {
            u32 ah0 = pH2[c0[i] + kb0], ah1 = pH2[c1[i] + kb0];
            u32 ah2 = pH2[c0[i] + kb1], ah3 = pH2[c1[i] + kb1];
            mma_f16(acc[i][0], ah0, ah1, ah2, ah3, q0.x, q0.y);
            mma_f16(acc[i][1], ah0, ah1, ah2, ah3, q1.x, q1.y);
            mma_f16(acc[i][2], ah0, ah1, ah2, ah3, q2.x, q2.y);
            mma_f16(acc[i][3], ah0, ah1, ah2, ah3, q3.x, q3.y);
        }
    }

    __syncthreads();                       // planes dead; reuse as u16 stage
    u16* stg = (u16*)(smem + MM_P);        // [484][33] u16
    #pragma unroll
    for (int i = 0; i < 4; i++) {
        int mt = w * 4 + i; if (mt > 30) mt = 30;
        int r0 = mt * 16 + (lane >> 2), r1 = r0 + 8;
        #pragma unroll
        for (int n = 0; n < 4; n++) {
            int oc = n * 8 + (lane & 3) * 2;
            if (oc < C2) {
                float s0 = sc2[oc], h0 = sh2[oc];
                float s1 = sc2[oc + 1], h1 = sh2[oc + 1];
                if (r0 < 484) {
                    stg[r0 * 33 + oc]     = f16_bits(fmaxf(acc[i][n][0] * s0 + h0, 0.f));
                    stg[r0 * 33 + oc + 1] = f16_bits(fmaxf(acc[i][n][1] * s1 + h1, 0.f));
                }
                if (r1 < 484) {
                    stg[r1 * 33 + oc]     = f16_bits(fmaxf(acc[i][n][2] * s0 + h0, 0.f));
                    stg[r1 * 33 + oc + 1] = f16_bits(fmaxf(acc[i][n][3] * s1 + h1, 0.f));
                }
            }
        }
    }
    __syncthreads();
    // ---- phase 5: 2x2 pool -> fc1 input (fp16) ----
    for (int i = t; i < 3630; i += 256) {
        int oc = i / 121, pos = i % 121;
        int py = pos / 11, px = pos % 11;
        int p00 = (2 * py) * 22 + 2 * px;
        float v = fmaxf(fmaxf(f16_val(stg[p00 * 33 + oc]),
                              f16_val(stg[(p00 + 1) * 33 + oc])),
                        fmaxf(f16_val(stg[(p00 + 22) * 33 + oc]),
                              f16_val(stg[(p00 + 23) * 33 + oc])));
        g_p2h[(size_t)b * FC1_IN + i] = f16_bits(v);
    }
}

// ---------------- kernel 3: FC1 via fp16 mma (1-term, K-split 8) ----------------
__global__ __launch_bounds__(256, 1) void fc1_mma_kernel()
{
    const int t = threadIdx.x, w = t >> 5, lane = t & 31;
    const int mt = blockIdx.x;
    const int kz = blockIdx.y;

    const int row0 = mt * 128 + w * 16 + (lane >> 2);
    const size_t base0 = (size_t)row0 * FC1_IN;
    const size_t base1 = (size_t)(row0 + 8) * FC1_IN;
    const int koff = (lane & 3) * 2;

    const int ks0 = kz * 28 + (kz < 3 ? kz : 3);
    const int nks = 28 + (kz < 3 ? 1 : 0);

    float acc[25][4];
    #pragma unroll
    for (int n = 0; n < 25; n++)
        { acc[n][0]=0.f; acc[n][1]=0.f; acc[n][2]=0.f; acc[n][3]=0.f; }

    #pragma unroll 1
    for (int ks = ks0; ks < ks0 + nks; ks++) {
        const int k0 = ks * 16 + koff;
        u32 ah0 = *(const u32*)&g_p2h[base0 + k0];
        u32 ah1 = *(const u32*)&g_p2h[base1 + k0];
        u32 ah2 = *(const u32*)&g_p2h[base0 + k0 + 8];
        u32 ah3 = *(const u32*)&g_p2h[base1 + k0 + 8];
        const uint2* bp = &g_W1frag[(size_t)ks * 25 * 32 + lane];
        #pragma unroll
        for (int n = 0; n < 25; n++) {
            uint2 q = bp[n * 32];
            mma_f16(acc[n], ah0, ah1, ah2, ah3, q.x, q.y);
        }
    }

    float* dst = g_fc1p + (size_t)kz * B * FC1_OUT;
    const int r0 = row0, r1 = row0 + 8;
    #pragma unroll
    for (int n = 0; n < 25; n++) {
        int o = n * 8 + (lane & 3) * 2;
        dst[(size_t)r0 * FC1_OUT + o]     = acc[n][0];
        dst[(size_t)r0 * FC1_OUT + o + 1] = acc[n][1];
        dst[(size_t)r1 * FC1_OUT + o]     = acc[n][2];
        dst[(size_t)r1 * FC1_OUT + o + 1] = acc[n][3];
    }
}

// ---------------- kernel 4: FC2 + sigmoid ----------------
__global__ __launch_bounds__(256) void fc2_kernel(
    const float* __restrict__ fc1b,
    const float* __restrict__ w2, const float* __restrict__ b2,
    float* __restrict__ out)
{
    const int warp = threadIdx.x >> 5, lane = threadIdx.x & 31;
    const int b = blockIdx.x * 8 + warp;
    const size_t PS = (size_t)B * FC1_OUT;
    const float* base = g_fc1p + (size_t)b * FC1_OUT;
    float s0 = 0.f, s1 = 0.f;
    for (int o = lane; o < FC1_OUT; o += 32) {
        float v = fc1b[o];
        #pragma unroll
        for (int p = 0; p < KSPLIT; p++)
            v += base[p * PS + o];
        v = fmaxf(v, 0.f);
        s0 += v * w2[o];
        s1 += v * w2[FC1_OUT + o];
    }
    #pragma unroll
    for (int d = 16; d > 0; d >>= 1) {
        s0 += __shfl_xor_sync(0xFFFFFFFFu, s0, d);
        s1 += __shfl_xor_sync(0xFFFFFFFFu, s1, d);
    }
    if (lane == 0) {
        out[2 * b + 0] = 1.f / (1.f + expf(-(s0 + b2[0])));
        out[2 * b + 1] = 1.f / (1.f + expf(-(s1 + b2[1])));
    }
}

// ---------------- launch ----------------
extern "C" void kernel_launch(void* const* d_in, const int* in_sizes, int n_in,
                              void* d_out, int out_size)
{
    const float* x       = (const float*)d_in[0];
    const float* log_s   = (const float*)d_in[1];
    const float* log_a   = (const float*)d_in[2];
    const float* log_d   = (const float*)d_in[3];
    const float* log_r   = (const float*)d_in[4];
    const float* conv1_w = (const float*)d_in[5];
    const float* conv1_b = (const float*)d_in[6];
    const float* bn1_g   = (const float*)d_in[7];
    const float* bn1_b   = (const float*)d_in[8];
    const float* bn1_m   = (const float*)d_in[9];
    const float* bn1_v   = (const float*)d_in[10];
    const float* conv2_w = (const float*)d_in[11];
    const float* conv2_b = (const float*)d_in[12];
    const float* bn2_g   = (const float*)d_in[13];
    const float* bn2_b   = (const float*)d_in[14];
    const float* bn2_m   = (const float*)d_in[15];
    const float* bn2_v   = (const float*)d_in[16];
    const float* fc1_w   = (const float*)d_in[17];
    const float* fc1_b   = (const float*)d_in[18];
    const float* fc2_w   = (const float*)d_in[19];
    const float* fc2_b   = (const float*)d_in[20];
    float* out = (float*)d_out;

    static int smem_set = 0;
    if (!smem_set) {
        cudaFuncSetAttribute(conv_fused_kernel,
                             cudaFuncAttributeMaxDynamicSharedMemorySize, MM_TOT);
        smem_set = 1;
    }

    prep_b_frag<<<(NKS2 * 128 + 255) / 256, 256>>>(conv2_w);
    prep_b1_frag<<<1, 256>>>(conv1_w);
    prep_w1_frag<<<(NKS1 * 25 * 32 + 255) / 256, 256>>>(fc1_w);
    conv_fused_kernel<<<B, 256, MM_TOT>>>(x, log_s, log_a, log_d, log_r,
                                          conv1_b, bn1_g, bn1_b, bn1_m, bn1_v,
                                          conv2_b, bn2_g, bn2_b, bn2_m, bn2_v);
    fc1_mma_kernel<<<dim3(16, KSPLIT), 256>>>();
    fc2_kernel<<<B / 8, 256>>>(fc1_b, fc2_w, fc2_b, out);
}

// round 15
// speedup vs baseline: 1.9729x; 1.0203x over previous
#include <cuda_runtime.h>
#include <cuda_fp16.h>
#include <math.h>
#include <stdint.h>

#define B 2048
#define C1 15
#define C2 30
#define P1 29
#define P2 11
#define FC1_IN (30*11*11)
#define FC1_OUT 200
#define KSPLIT 8
#define NKS1 227              // ceil(3630/16)
#define NKS2 53               // ceil(105/2) conv2 row-pair k-steps
#define NFC1 (NKS1*25*32)     // 181600 fc1 frag elements

typedef uint16_t u16;
typedef uint32_t u32;

// ---------------- warp mma m16n8k16 fp16 -> f32 ----------------
__device__ __forceinline__ void mma_f16(float* d, u32 a0, u32 a1, u32 a2, u32 a3,
                                        u32 b0, u32 b1) {
    asm volatile(
        "mma.sync.aligned.m16n8k16.row.col.f32.f16.f16.f32 "
        "{%0,%1,%2,%3}, {%4,%5,%6,%7}, {%8,%9}, {%0,%1,%2,%3};"
        : "+f"(d[0]), "+f"(d[1]), "+f"(d[2]), "+f"(d[3])
        : "r"(a0), "r"(a1), "r"(a2), "r"(a3), "r"(b0), "r"(b1));
}

__device__ __forceinline__ u16 f16_bits(float v) {
    return __half_as_ushort(__float2half(v));
}
__device__ __forceinline__ float f16_val(u16 b) {
    return __half2float(__ushort_as_half(b));
}

// ---------------- scratch ----------------
__device__ float g_fc1p[KSPLIT * B * FC1_OUT];
__device__ __align__(4)  u16  g_p2h[B * FC1_IN + 64];           // conv2 out, fp16
__device__ __align__(16) uint2 g_Bfrag2[NKS2 * 4 * 32];         // conv2 W frags
__device__ __align__(16) uint2 g_B1frag[2 * 4 * 32];            // conv1 W frags
__device__ __align__(16) uint2 g_W1frag[NKS1 * 25 * 32];        // fc1 W frags

// ---------------- kernel 0: prep ALL weight fragments ----------------
__global__ void prep_all_frags(const float* __restrict__ w1,
                               const float* __restrict__ w2,
                               const float* __restrict__ wf)
{
    int idx = blockIdx.x * 256 + threadIdx.x;

    if (idx < NFC1) {
        // fc1 fragments
        int lane = idx & 31;
        int nt = (idx >> 5) % 25;
        int ks = idx / (25 * 32);
        int o = nt * 8 + (lane >> 2);
        int k0 = ks * 16 + (lane & 3) * 2;
        const float* wr = wf + (size_t)o * FC1_IN;
        float v[4];
        v[0] = (k0     < FC1_IN) ? wr[k0]     : 0.f;
        v[1] = (k0 + 1 < FC1_IN) ? wr[k0 + 1] : 0.f;
        v[2] = (k0 + 8 < FC1_IN) ? wr[k0 + 8] : 0.f;
        v[3] = (k0 + 9 < FC1_IN) ? wr[k0 + 9] : 0.f;
        uint2 q;
        q.x = (u32)f16_bits(v[0]) | ((u32)f16_bits(v[1]) << 16);
        q.y = (u32)f16_bits(v[2]) | ((u32)f16_bits(v[3]) << 16);
        g_W1frag[idx] = q;
        return;
    }
    idx -= NFC1;
    if (idx < NKS2 * 128) {
        // conv2 fragments (row-pair packed)
        int lane = idx & 31, nt = (idx >> 5) & 3, ks = idx >> 7;
        int oc = nt * 8 + (lane >> 2), k0 = (lane & 3) * 2;
        int rA = 2 * ks, rB = rA + 1;
        float v[4] = {0.f, 0.f, 0.f, 0.f};
        if (oc < C2) {
            int icA = rA / 7, dyA = rA % 7;
            const float* wa = w2 + ((oc * C1 + icA) * 7 + dyA) * 7;
            v[0] = wa[k0];
            if (k0 + 1 < 7) v[1] = wa[k0 + 1];
            if (rB <= 104) {
                int icB = rB / 7, dyB = rB % 7;
                const float* wb = w2 + ((oc * C1 + icB) * 7 + dyB) * 7;
                v[2] = wb[k0];
                if (k0 + 1 < 7) v[3] = wb[k0 + 1];
            }
        }
        uint2 q;
        q.x = (u32)f16_bits(v[0]) | ((u32)f16_bits(v[1]) << 16);
        q.y = (u32)f16_bits(v[2]) | ((u32)f16_bits(v[3]) << 16);
        g_Bfrag2[idx] = q;
        return;
    }
    idx -= NKS2 * 128;
    if (idx < 256) {
        // conv1 fragments
        int lane = idx & 31, ks = (idx >> 5) & 3, nt = idx >> 7;
        int oc = nt * 8 + (lane >> 2), k0 = (lane & 3) * 2;
        int dy0 = ks * 2, dy1 = dy0 + 1;
        float v[4] = {0.f, 0.f, 0.f, 0.f};
        if (oc < C1) {
            const float* wb = w1 + oc * 49;
            v[0] = wb[dy0 * 7 + k0];
            if (k0 + 1 < 7) v[1] = wb[dy0 * 7 + k0 + 1];
            if (dy1 < 7) {
                v[2] = wb[dy1 * 7 + k0];
                if (k0 + 1 < 7) v[3] = wb[dy1 * 7 + k0 + 1];
            }
        }
        uint2 q;
        q.x = (u32)f16_bits(v[0]) | ((u32)f16_bits(v[1]) << 16);
        q.y = (u32)f16_bits(v[2]) | ((u32)f16_bits(v[3]) << 16);
        g_B1frag[(nt * 4 + ks) * 32 + lane] = q;
    }
}

// ---------------- kernel 1: fused PCEN + conv1 + conv2 + pools ----------------
#define PL1 2112                 // u32 per conv1 parity copy
#define PL2 6960                 // u32 per conv2 parity copy
#define MM_P    0
#define MM_IMG  55680
#define MM_C1P  72320
#define MM_SC1  89216
#define MM_SH1  89280
#define MM_SC2  89344
#define MM_SH2  89472
#define MM_RT   89600
#define MM_TOT  90112

__global__ __launch_bounds__(256, 2) void conv_fused_kernel(
    const float* __restrict__ x,
    const float* __restrict__ log_s, const float* __restrict__ log_alpha,
    const float* __restrict__ log_delta, const float* __restrict__ log_r,
    const float* __restrict__ b1,
    const float* __restrict__ g1,  const float* __restrict__ be1,
    const float* __restrict__ mu1, const float* __restrict__ va1,
    const float* __restrict__ b2,
    const float* __restrict__ g2,  const float* __restrict__ be2,
    const float* __restrict__ mu2, const float* __restrict__ va2)
{
    extern __shared__ __align__(16) char smem[];
    u16* pP16 = (u16*)(smem + MM_P);             // conv2 planes (even @0, odd @13920)
    const u32* pH2 = (const u32*)(smem + MM_P);
    float* img = (float*)(smem + MM_IMG);
    u16* c1E16 = (u16*)(smem + MM_C1P);
    const u32* pH1 = (const u32*)(smem + MM_C1P);
    float* sc1 = (float*)(smem + MM_SC1);
    float* sh1 = (float*)(smem + MM_SH1);
    float* sc2 = (float*)(smem + MM_SC2);
    float* sh2 = (float*)(smem + MM_SH2);
    int* rowTab = (int*)(smem + MM_RT);

    const int b = blockIdx.x, t = threadIdx.x;
    const int w = t >> 5, lane = t & 31;
    const float* xb = x + (size_t)b * 4096;

    // ---- phase 0: loads + consts ----
    for (int i = t; i < 4096; i += 256)
        img[(i >> 6) * 65 + (i & 63)] = xb[i];
    {
        uint4* pz = (uint4*)(smem + MM_P);
        uint4 z = make_uint4(0u, 0u, 0u, 0u);
        for (int i = t; i < 3480; i += 256) pz[i] = z;   // zero conv2 planes
    }
    if (t < 16) {
        if (t < C1) {
            float inv = g1[t] * rsqrtf(va1[t] + 1e-5f);
            sc1[t] = inv;
            sh1[t] = (b1[t] - mu1[t]) * inv + be1[t];
        } else { sc1[t] = 0.f; sh1[t] = 0.f; }
    }
    if (t >= 32 && t < 32 + C2) {
        int c = t - 32;
        float inv = g2[c] * rsqrtf(va2[c] + 1e-5f);
        sc2[c] = inv;
        sh2[c] = (b2[c] - mu2[c]) * inv + be2[c];
    }
    if (t >= 64 && t < 170) {
        int i = t - 64;
        int r = (i < 105) ? i : 104;
        rowTab[i] = ((r / 7) * 29 + (r % 7)) * 16;
    }
    uint2 qf[2][4];
    #pragma unroll
    for (int nt = 0; nt < 2; nt++)
        #pragma unroll
        for (int ks = 0; ks < 4; ks++)
            qf[nt][ks] = g_B1frag[(nt * 4 + ks) * 32 + lane];
    __syncthreads();

    // ---- phase 1: PCEN, 4-way segmented scan (all 256 threads) ----
    {
        const float s     = expf(log_s[0]);
        const float alpha = expf(log_alpha[0]);
        const float delta = expf(log_delta[0]);
        const float r     = expf(log_r[0]);
        const float oms   = 1.0f - s;
        const float dr    = powf(delta, r);
        const float oms16 = powf(oms, 16.0f);
        const float oms32 = oms16 * oms16;

        const int seg = t & 3;
        float* xs = img + (t >> 2) * 65 + seg * 16;

        // pass 1: local EMA from zero
        float m = 0.0f;
        #pragma unroll
        for (int i = 0; i < 16; i++) m = oms * m + s * xs[i];

        // inclusive scan across the 4 segments of this row (lanes 4q..4q+3)
        float up1 = __shfl_up_sync(0xFFFFFFFFu, m, 1);
        if (seg >= 1) m += oms16 * up1;
        float up2 = __shfl_up_sync(0xFFFFFFFFu, m, 2);
        if (seg >= 2) m += oms32 * up2;
        float m_in = __shfl_up_sync(0xFFFFFFFFu, m, 1);
        if (seg == 0) m_in = 0.0f;

        // pass 2: recompute with correct incoming state + transform
        m = m_in;
        #pragma unroll 4
        for (int i = 0; i < 16; i++) {
            float xv = xs[i];
            m = oms * m + s * xv;
            float Ma = __powf(m + 1e-6f, alpha);
            xs[i] = __powf(__fdividef(xv, Ma) + delta, r) - dr;
        }
    }
    __syncthreads();

    // ---- phase 2: conv1 parity planes (zero tail rows 64..65) ----
    {
        u16* c1O16 = c1E16 + 4224;
        for (int i = t; i < 4224; i += 256) {
            u16 h = 0;
            if (i < 4096) h = f16_bits(img[(i >> 6) * 65 + (i & 63)]);
            c1E16[i] = h;
            if (i > 0) c1O16[i - 1] = h;
        }
        if (t == 0) c1O16[4223] = 0;
    }
    __syncthreads();

    // ---- phase 3: conv1 MMA + BN/ReLU/pool -> conv2 planes ----
    {
        const int r = lane >> 2;
        const int koff = (lane & 3) * 2;
        for (int mt = w; mt < 232; mt += 8) {
            const int py = mt >> 3, xo = mt & 7;
            const int y0 = 2 * py, x0 = xo * 8;
            const int eA = y0 * 64 + x0 + r + koff;
            int i0 = (eA & 1) * PL1 + (eA >> 1);

            float acc[2][4];
            #pragma unroll
            for (int nt = 0; nt < 2; nt++)
                { acc[nt][0]=0.f; acc[nt][1]=0.f; acc[nt][2]=0.f; acc[nt][3]=0.f; }

            u32 hA = pH1[i0];
            #pragma unroll
            for (int ks = 0; ks < 4; ks++) {
                u32 hB = pH1[i0 + 32];
                u32 hC = pH1[i0 + 64];
                #pragma unroll
                for (int nt = 0; nt < 2; nt++)
                    mma_f16(acc[nt], hA, hB, hB, hC, qf[nt][ks].x, qf[nt][ks].y);
                hA = hC;
                i0 += 64;
            }

            #pragma unroll
            for (int nt = 0; nt < 2; nt++) {
                int oc = nt * 8 + (lane & 3) * 2;
                float s0 = sc1[oc], h0 = sh1[oc];
                float s1 = sc1[oc + 1], h1 = sh1[oc + 1];
                float m0 = fmaxf(fmaxf(acc[nt][0] * s0 + h0, 0.f),
                                 fmaxf(acc[nt][2] * s0 + h0, 0.f));
                float m1 = fmaxf(fmaxf(acc[nt][1] * s1 + h1, 0.f),
                                 fmaxf(acc[nt][3] * s1 + h1, 0.f));
                m0 = fmaxf(m0, __shfl_xor_sync(0xFFFFFFFFu, m0, 4));
                m1 = fmaxf(m1, __shfl_xor_sync(0xFFFFFFFFu, m1, 4));
                if (!(r & 1)) {
                    int px = (x0 + r) >> 1;
                    if (px < P1) {
                        if (oc < C1) {
                            int e = oc * 928 + py * 32 + px;
                            u16 hv = f16_bits(m0);
                            pP16[e] = hv;
                            if (e > 0) pP16[13920 + e - 1] = hv;
                        }
                        if (oc + 1 < C1) {
                            int e = (oc + 1) * 928 + py * 32 + px;
                            u16 hv = f16_bits(m1);
                            pP16[e] = hv;
                            pP16[13920 + e - 1] = hv;
                        }
                    }
                }
            }
        }
    }
    __syncthreads();

    // ---- phase 4: conv2 MMA (software-pipelined frag loads) ----
    int c0[4], c1[4];
    #pragma unroll
    for (int i = 0; i < 4; i++) {
        int mt = w * 4 + i; if (mt > 30) mt = 30;
        int p0 = mt * 16 + (lane >> 2); if (p0 > 483) p0 = 483;
        int p1 = p0 + 8;                if (p1 > 483) p1 = 483;
        int y0 = p0 / 22, x0 = p0 - y0 * 22;
        int y1 = p1 / 22, x1 = p1 - y1 * 22;
        int dx0 = (lane & 3) * 2;
        c0[i] = (x0 & 1) * PL2 + y0 * 16 + ((x0 + dx0 - (x0 & 1)) >> 1);
        c1[i] = (x1 & 1) * PL2 + y1 * 16 + ((x1 + dx0 - (x1 & 1)) >> 1);
    }

    float acc[4][4][4];
    #pragma unroll
    for (int i = 0; i < 4; i++)
        #pragma unroll
        for (int n = 0; n < 4; n++)
            { acc[i][n][0]=0.f; acc[i][n][1]=0.f; acc[i][n][2]=0.f; acc[i][n][3]=0.f; }

    uint2 q0 = g_Bfrag2[0 * 32 + lane];
    uint2 q1 = g_Bfrag2[1 * 32 + lane];
    uint2 q2 = g_Bfrag2[2 * 32 + lane];
    uint2 q3 = g_Bfrag2[3 * 32 + lane];

    #pragma unroll 1
    for (int j = 0; j < NKS2; j++) {
        const int kb0 = rowTab[2 * j];
        const int kb1 = rowTab[2 * j + 1];
        uint2 n0, n1, n2, n3;
        if (j + 1 < NKS2) {
            n0 = g_Bfrag2[((j + 1) * 4 + 0) * 32 + lane];
            n1 = g_Bfrag2[((j + 1) * 4 + 1) * 32 + lane];
            n2 = g_Bfrag2[((j + 1) * 4 + 2) * 32 + lane];
            n3 = g_Bfrag2[((j + 1) * 4 + 3) * 32 + lane];
        }
        #pragma unroll
        for (int i = 0; i < 4; i++) {
            u32 ah0 = pH2[c0[i] + kb0], ah1 = pH2[c1[i] + kb0];
            u32 ah2 = pH2[c0[i] + kb1], ah3 = pH2[c1[i] + kb1];
            mma_f16(acc[i][0], ah0, ah1, ah2, ah3, q0.x, q0.y);
            mma_f16(acc[i][1], ah0, ah1, ah2, ah3, q1.x, q1.y);
            mma_f16(acc[i][2], ah0, ah1, ah2, ah3, q2.x, q2.y);
            mma_f16(acc[i][3], ah0, ah1, ah2, ah3, q3.x, q3.y);
        }
        q0 = n0; q1 = n1; q2 = n2; q3 = n3;
    }

    __syncthreads();                       // planes dead; reuse as u16 stage
    u16* stg = (u16*)(smem + MM_P);        // [484][33] u16
    #pragma unroll
    for (int i = 0; i < 4; i++) {
        int mt = w * 4 + i; if (mt > 30) mt = 30;
        int r0 = mt * 16 + (lane >> 2), r1 = r0 + 8;
        #pragma unroll
        for (int n = 0; n < 4; n++) {
            int oc = n * 8 + (lane & 3) * 2;
            if (oc < C2) {
                float s0 = sc2[oc], h0 = sh2[oc];
                float s1 = sc2[oc + 1], h1 = sh2[oc + 1];
                if (r0 < 484) {
                    stg[r0 * 33 + oc]     = f16_bits(fmaxf(acc[i][n][0] * s0 + h0, 0.f));
                    stg[r0 * 33 + oc + 1] = f16_bits(fmaxf(acc[i][n][1] * s1 + h1, 0.f));
                }
                if (r1 < 484) {
                    stg[r1 * 33 + oc]     = f16_bits(fmaxf(acc[i][n][2] * s0 + h0, 0.f));
                    stg[r1 * 33 + oc + 1] = f16_bits(fmaxf(acc[i][n][3] * s1 + h1, 0.f));
                }
            }
        }
    }
    __syncthreads();
    // ---- phase 5: 2x2 pool -> fc1 input (fp16) ----
    for (int i = t; i < 3630; i += 256) {
        int oc = i / 121, pos = i % 121;
        int py = pos / 11, px = pos % 11;
        int p00 = (2 * py) * 22 + 2 * px;
        float v = fmaxf(fmaxf(f16_val(stg[p00 * 33 + oc]),
                              f16_val(stg[(p00 + 1) * 33 + oc])),
                        fmaxf(f16_val(stg[(p00 + 22) * 33 + oc]),
                              f16_val(stg[(p00 + 23) * 33 + oc])));
        g_p2h[(size_t)b * FC1_IN + i] = f16_bits(v);
    }
}

// ---------------- kernel 2: FC1 via fp16 mma (1-term, K-split 8) ----------------
__global__ __launch_bounds__(256, 1) void fc1_mma_kernel()
{
    const int t = threadIdx.x, w = t >> 5, lane = t & 31;
    const int mt = blockIdx.x;
    const int kz = blockIdx.y;

    const int row0 = mt * 128 + w * 16 + (lane >> 2);
    const size_t base0 = (size_t)row0 * FC1_IN;
    const size_t base1 = (size_t)(row0 + 8) * FC1_IN;
    const int koff = (lane & 3) * 2;

    const int ks0 = kz * 28 + (kz < 3 ? kz : 3);
    const int nks = 28 + (kz < 3 ? 1 : 0);

    float acc[25][4];
    #pragma unroll
    for (int n = 0; n < 25; n++)
        { acc[n][0]=0.f; acc[n][1]=0.f; acc[n][2]=0.f; acc[n][3]=0.f; }

    #pragma unroll 1
    for (int ks = ks0; ks < ks0 + nks; ks++) {
        const int k0 = ks * 16 + koff;
        u32 ah0 = *(const u32*)&g_p2h[base0 + k0];
        u32 ah1 = *(const u32*)&g_p2h[base1 + k0];
        u32 ah2 = *(const u32*)&g_p2h[base0 + k0 + 8];
        u32 ah3 = *(const u32*)&g_p2h[base1 + k0 + 8];
        const uint2* bp = &g_W1frag[(size_t)ks * 25 * 32 + lane];
        #pragma unroll
        for (int n = 0; n < 25; n++) {
            uint2 q = bp[n * 32];
            mma_f16(acc[n], ah0, ah1, ah2, ah3, q.x, q.y);
        }
    }

    float* dst = g_fc1p + (size_t)kz * B * FC1_OUT;
    const int r0 = row0, r1 = row0 + 8;
    #pragma unroll
    for (int n = 0; n < 25; n++) {
        int o = n * 8 + (lane & 3) * 2;
        dst[(size_t)r0 * FC1_OUT + o]     = acc[n][0];
        dst[(size_t)r0 * FC1_OUT + o + 1] = acc[n][1];
        dst[(size_t)r1 * FC1_OUT + o]     = acc[n][2];
        dst[(size_t)r1 * FC1_OUT + o + 1] = acc[n][3];
    }
}

// ---------------- kernel 3: FC2 + sigmoid ----------------
__global__ __launch_bounds__(256) void fc2_kernel(
    const float* __restrict__ fc1b,
    const float* __restrict__ w2, const float* __restrict__ b2,
    float* __restrict__ out)
{
    const int warp = threadIdx.x >> 5, lane = threadIdx.x & 31;
    const int b = blockIdx.x * 8 + warp;
    const size_t PS = (size_t)B * FC1_OUT;
    const float* base = g_fc1p + (size_t)b * FC1_OUT;
    float s0 = 0.f, s1 = 0.f;
    for (int o = lane; o < FC1_OUT; o += 32) {
        float v = fc1b[o];
        #pragma unroll
        for (int p = 0; p < KSPLIT; p++)
            v += base[p * PS + o];
        v = fmaxf(v, 0.f);
        s0 += v * w2[o];
        s1 += v * w2[FC1_OUT + o];
    }
    #pragma unroll
    for (int d = 16; d > 0; d >>= 1) {
        s0 += __shfl_xor_sync(0xFFFFFFFFu, s0, d);
        s1 += __shfl_xor_sync(0xFFFFFFFFu, s1, d);
    }
    if (lane == 0) {
        out[2 * b + 0] = 1.f / (1.f + expf(-(s0 + b2[0])));
        out[2 * b + 1] = 1.f / (1.f + expf(-(s1 + b2[1])));
    }
}

// ---------------- launch ----------------
extern "C" void kernel_launch(void* const* d_in, const int* in_sizes, int n_in,
                              void* d_out, int out_size)
{
    const float* x       = (const float*)d_in[0];
    const float* log_s   = (const float*)d_in[1];
    const float* log_a   = (const float*)d_in[2];
    const float* log_d   = (const float*)d_in[3];
    const float* log_r   = (const float*)d_in[4];
    const float* conv1_w = (const float*)d_in[5];
    const float* conv1_b = (const float*)d_in[6];
    const float* bn1_g   = (const float*)d_in[7];
    const float* bn1_b   = (const float*)d_in[8];
    const float* bn1_m   = (const float*)d_in[9];
    const float* bn1_v   = (const float*)d_in[10];
    const float* conv2_w = (const float*)d_in[11];
    const float* conv2_b = (const float*)d_in[12];
    const float* bn2_g   = (const float*)d_in[13];
    const float* bn2_b   = (const float*)d_in[14];
    const float* bn2_m   = (const float*)d_in[15];
    const float* bn2_v   = (const float*)d_in[16];
    const float* fc1_w   = (const float*)d_in[17];
    const float* fc1_b   = (const float*)d_in[18];
    const float* fc2_w   = (const float*)d_in[19];
    const float* fc2_b   = (const float*)d_in[20];
    float* out = (float*)d_out;

    static int smem_set = 0;
    if (!smem_set) {
        cudaFuncSetAttribute(conv_fused_kernel,
                             cudaFuncAttributeMaxDynamicSharedMemorySize, MM_TOT);
        smem_set = 1;
    }

    const int prep_total = NFC1 + NKS2 * 128 + 256;
    prep_all_frags<<<(prep_total + 255) / 256, 256>>>(conv1_w, conv2_w, fc1_w);
    conv_fused_kernel<<<B, 256, MM_TOT>>>(x, log_s, log_a, log_d, log_r,
                                          conv1_b, bn1_g, bn1_b, bn1_m, bn1_v,
                                          conv2_b, bn2_g, bn2_b, bn2_m, bn2_v);
    fc1_mma_kernel<<<dim3(16, KSPLIT), 256>>>();
    fc2_kernel<<<B / 8, 256>>>(fc1_b, fc2_w, fc2_b, out);
}